// round 8
// baseline (speedup 1.0000x reference)
#include <cuda_runtime.h>
#include <cstdint>

#define Bc 2
#define Tc 2048
#define Cc 1024
#define Hc 16
#define Dc 64

__device__ float g_q[Bc * Hc * Tc * Dc];
__device__ float g_k[Bc * Hc * Tc * Dc];
__device__ float g_v[Bc * Hc * Tc * Dc];
__device__ float g_y[Bc * Tc * Cc];

// ---------------- packed f32x2 helpers ----------------
typedef unsigned long long u64t;
__device__ __forceinline__ u64t ffma2(u64t a, u64t b, u64t c) {
    u64t d; asm("fma.rn.f32x2 %0, %1, %2, %3;" : "=l"(d) : "l"(a), "l"(b), "l"(c)); return d;
}
__device__ __forceinline__ u64t fmul2(u64t a, u64t b) {
    u64t d; asm("mul.rn.f32x2 %0, %1, %2;" : "=l"(d) : "l"(a), "l"(b)); return d;
}
__device__ __forceinline__ u64t pk2(float x, float y) {
    u64t r; asm("mov.b64 %0, {%1, %2};" : "=l"(r) : "f"(x), "f"(y)); return r;
}
__device__ __forceinline__ void up2(u64t v, float& x, float& y) {
    asm("mov.b64 {%0, %1}, %2;" : "=f"(x), "=f"(y) : "l"(v));
}

// ============================================================================
// NT GEMM: C[m,n] = sum_k A[m,k]*B[n,k] + bias[n]. fp32, f32x2-packed FMA.
// CTA 128x128, K chunk 16, DOUBLE-BUFFERED smem (1 sync/chunk), stride-132
// padded tiles (2-way max STS conflicts, aligned LDS.128 reads).
// MODE 0: scatter [B,H,T,D]; 1: row-major [M,N].
// ============================================================================
#define GBM 128
#define GBN 128
#define GBK 16
#define GPAD 132

template <int MODE>
__global__ void __launch_bounds__(256)
gemm_nt(const float* __restrict__ A, const float* __restrict__ B,
        const float* __restrict__ bias, float* __restrict__ C,
        int M, int N, int K)
{
    __shared__ __align__(16) float As[2][GBK][GPAD];
    __shared__ __align__(16) float Bs[2][GBK][GPAD];

    const int tid = threadIdx.x;
    const int m0 = blockIdx.y * GBM;
    const int n0 = blockIdx.x * GBN;
    const int row = (tid >> 4) << 3;
    const int col = (tid & 15) << 3;

    u64t acc2[8][4];
#pragma unroll
    for (int i = 0; i < 8; i++)
#pragma unroll
        for (int j = 0; j < 4; j++) acc2[i][j] = 0ull;

    float4 ra[2], rb[2];
    // prefetch chunk 0 into regs
#pragma unroll
    for (int it = 0; it < 2; it++) {
        int e = tid + it * 256;
        int r = e >> 2, c4 = (e & 3) << 2;
        ra[it] = *reinterpret_cast<const float4*>(&A[(size_t)(m0 + r) * K + c4]);
        rb[it] = *reinterpret_cast<const float4*>(&B[(size_t)(n0 + r) * K + c4]);
    }
    // store chunk 0 into buf 0
#pragma unroll
    for (int it = 0; it < 2; it++) {
        int e = tid + it * 256;
        int r = e >> 2, c4 = (e & 3) << 2;
        As[0][c4 + 0][r] = ra[it].x; As[0][c4 + 1][r] = ra[it].y;
        As[0][c4 + 2][r] = ra[it].z; As[0][c4 + 3][r] = ra[it].w;
        Bs[0][c4 + 0][r] = rb[it].x; Bs[0][c4 + 1][r] = rb[it].y;
        Bs[0][c4 + 2][r] = rb[it].z; Bs[0][c4 + 3][r] = rb[it].w;
    }
    __syncthreads();

    const int nch = K / GBK;
    for (int ch = 0; ch < nch; ch++) {
        const int cur = ch & 1;
        // LDG next chunk into regs (latency overlapped with compute below)
        if (ch + 1 < nch) {
            int k0 = (ch + 1) * GBK;
#pragma unroll
            for (int it = 0; it < 2; it++) {
                int e = tid + it * 256;
                int r = e >> 2, c4 = (e & 3) << 2;
                ra[it] = *reinterpret_cast<const float4*>(&A[(size_t)(m0 + r) * K + k0 + c4]);
                rb[it] = *reinterpret_cast<const float4*>(&B[(size_t)(n0 + r) * K + k0 + c4]);
            }
        }

        // compute on buf cur
#pragma unroll
        for (int k = 0; k < GBK; k++) {
            float a[8];
            *reinterpret_cast<float4*>(&a[0]) = *reinterpret_cast<const float4*>(&As[cur][k][row]);
            *reinterpret_cast<float4*>(&a[4]) = *reinterpret_cast<const float4*>(&As[cur][k][row + 4]);
            ulonglong2 b01 = *reinterpret_cast<const ulonglong2*>(&Bs[cur][k][col]);
            ulonglong2 b23 = *reinterpret_cast<const ulonglong2*>(&Bs[cur][k][col + 4]);
            u64t bb[4] = {b01.x, b01.y, b23.x, b23.y};
#pragma unroll
            for (int i = 0; i < 8; i++) {
                u64t ad = pk2(a[i], a[i]);
#pragma unroll
                for (int j = 0; j < 4; j++) acc2[i][j] = ffma2(ad, bb[j], acc2[i][j]);
            }
        }

        // store next chunk into the other buffer (tile ch-1 readers are done:
        // last read of buf cur^1 was before the sync that ended chunk ch-1)
        if (ch + 1 < nch) {
            const int nxt = cur ^ 1;
#pragma unroll
            for (int it = 0; it < 2; it++) {
                int e = tid + it * 256;
                int r = e >> 2, c4 = (e & 3) << 2;
                As[nxt][c4 + 0][r] = ra[it].x; As[nxt][c4 + 1][r] = ra[it].y;
                As[nxt][c4 + 2][r] = ra[it].z; As[nxt][c4 + 3][r] = ra[it].w;
                Bs[nxt][c4 + 0][r] = rb[it].x; Bs[nxt][c4 + 1][r] = rb[it].y;
                Bs[nxt][c4 + 2][r] = rb[it].z; Bs[nxt][c4 + 3][r] = rb[it].w;
            }
        }
        __syncthreads();
    }

#pragma unroll
    for (int i = 0; i < 8; i++) {
        int m = m0 + row + i;
        float v[8];
#pragma unroll
        for (int j = 0; j < 4; j++) up2(acc2[i][j], v[2 * j], v[2 * j + 1]);
#pragma unroll
        for (int j = 0; j < 8; j++) {
            int n = n0 + col + j;
            float val = v[j] + bias[n];
            if (MODE == 0) {
                int bb = m >> 11, tt = m & 2047, hh = n >> 6, dd = n & 63;
                C[((size_t)((bb * Hc + hh) * Tc + tt) << 6) + dd] = val;
            } else {
                C[(size_t)m * N + n] = val;
            }
        }
    }
}

// ============================================================================
// Flash attention fp32, causal, 64q x 64kv tiles, 256 threads.
// (Unchanged from the validated 677us version.)
// ============================================================================
__device__ __forceinline__ int swf(int row, int c4) {
    return (row << 4) + (c4 ^ ((row + (row >> 4)) & 15));
}

#define FSMEM_BYTES (4 * 64 * 64 * 4)   // Qs,Ks,Vs,Ps = 64KB

__global__ void __launch_bounds__(256)
flash_attn(const float* __restrict__ Q, const float* __restrict__ K,
           const float* __restrict__ V, float* __restrict__ Y)
{
    extern __shared__ __align__(16) float fs[];
    float* Qs = fs;
    float* Ks = fs + 4096;
    float* Vs = fs + 8192;
    float* Ps = fs + 12288;

    const int bh  = blockIdx.y;
    const int b   = bh >> 4;
    const int h   = bh & 15;
    const int qtile = gridDim.x - 1 - blockIdx.x;
    const int m0  = qtile << 6;
    const int tid = threadIdx.x;
    const int qg  = tid >> 4;
    const int kg  = tid & 15;
    const int q0  = qg << 2;
    const size_t base = (size_t)bh * Tc * Dc;

#pragma unroll
    for (int it = 0; it < 4; it++) {
        int e = tid + (it << 8);
        int rr = e >> 4, c4 = e & 15;
        float4 v = *(const float4*)&Q[base + (size_t)(m0 + rr) * Dc + (c4 << 2)];
        v.x *= 0.125f; v.y *= 0.125f; v.z *= 0.125f; v.w *= 0.125f;
        ((float4*)Qs)[swf(rr, c4)] = v;
    }

    u64t acc2[4][2];
#pragma unroll
    for (int i = 0; i < 4; i++) { acc2[i][0] = 0ull; acc2[i][1] = 0ull; }
    float m[4], l[4];
#pragma unroll
    for (int i = 0; i < 4; i++) { m[i] = -1e30f; l[i] = 0.f; }

    const int nkv = qtile + 1;
    for (int j = 0; j < nkv; j++) {
        const int n0 = j << 6;
        __syncthreads();
#pragma unroll
        for (int it = 0; it < 4; it++) {
            int e = tid + (it << 8);
            int rr = e >> 4, c4 = e & 15;
            ((float4*)Ks)[swf(rr, c4)] =
                *(const float4*)&K[base + (size_t)(n0 + rr) * Dc + (c4 << 2)];
            ((float4*)Vs)[swf(rr, c4)] =
                *(const float4*)&V[base + (size_t)(n0 + rr) * Dc + (c4 << 2)];
        }
        __syncthreads();

        u64t s2[4][4];
#pragma unroll
        for (int qi = 0; qi < 4; qi++)
#pragma unroll
            for (int kj = 0; kj < 4; kj++) s2[qi][kj] = 0ull;
#pragma unroll
        for (int c4 = 0; c4 < 16; c4++) {
            ulonglong2 q2[4], k2[4];
#pragma unroll
            for (int qi = 0; qi < 4; qi++)
                q2[qi] = ((const ulonglong2*)Qs)[swf(q0 + qi, c4)];
#pragma unroll
            for (int kj = 0; kj < 4; kj++)
                k2[kj] = ((const ulonglong2*)Ks)[swf((kg << 2) + kj, c4)];
#pragma unroll
            for (int qi = 0; qi < 4; qi++)
#pragma unroll
                for (int kj = 0; kj < 4; kj++) {
                    s2[qi][kj] = ffma2(q2[qi].x, k2[kj].x, s2[qi][kj]);
                    s2[qi][kj] = ffma2(q2[qi].y, k2[kj].y, s2[qi][kj]);
                }
        }
        float s[4][4];
#pragma unroll
        for (int qi = 0; qi < 4; qi++)
#pragma unroll
            for (int kj = 0; kj < 4; kj++) {
                float a, bb; up2(s2[qi][kj], a, bb);
                s[qi][kj] = a + bb;
            }

        if (j == nkv - 1) {
#pragma unroll
            for (int qi = 0; qi < 4; qi++)
#pragma unroll
                for (int kj = 0; kj < 4; kj++)
                    if (((kg << 2) + kj) > (q0 + qi)) s[qi][kj] = -1e30f;
        }

        float mx[4];
#pragma unroll
        for (int qi = 0; qi < 4; qi++)
            mx[qi] = fmaxf(fmaxf(s[qi][0], s[qi][1]), fmaxf(s[qi][2], s[qi][3]));
#pragma unroll
        for (int off = 1; off < 16; off <<= 1)
#pragma unroll
            for (int qi = 0; qi < 4; qi++)
                mx[qi] = fmaxf(mx[qi], __shfl_xor_sync(0xffffffffu, mx[qi], off));

        float alpha[4], sum[4];
#pragma unroll
        for (int qi = 0; qi < 4; qi++) {
            float mn = fmaxf(m[qi], mx[qi]);
            alpha[qi] = __expf(m[qi] - mn);
            m[qi] = mn;
            float t0 = __expf(s[qi][0] - mn);
            float t1 = __expf(s[qi][1] - mn);
            float t2 = __expf(s[qi][2] - mn);
            float t3 = __expf(s[qi][3] - mn);
            s[qi][0] = t0; s[qi][1] = t1; s[qi][2] = t2; s[qi][3] = t3;
            sum[qi] = (t0 + t1) + (t2 + t3);
        }
#pragma unroll
        for (int off = 1; off < 16; off <<= 1)
#pragma unroll
            for (int qi = 0; qi < 4; qi++)
                sum[qi] += __shfl_xor_sync(0xffffffffu, sum[qi], off);
#pragma unroll
        for (int qi = 0; qi < 4; qi++) {
            l[qi] = l[qi] * alpha[qi] + sum[qi];
            u64t a2 = pk2(alpha[qi], alpha[qi]);
            acc2[qi][0] = fmul2(acc2[qi][0], a2);
            acc2[qi][1] = fmul2(acc2[qi][1], a2);
        }

#pragma unroll
        for (int kj = 0; kj < 4; kj++) {
            float4 pv = make_float4(s[0][kj], s[1][kj], s[2][kj], s[3][kj]);
            ((float4*)Ps)[swf((kg << 2) + kj, qg)] = pv;
        }
        __syncthreads();

#pragma unroll 8
        for (int c = 0; c < 64; c++) {
            float4 p4 = ((const float4*)Ps)[swf(c, qg)];
            ulonglong2 v2 = ((const ulonglong2*)Vs)[swf(c, kg)];
            u64t pd;
            pd = pk2(p4.x, p4.x);
            acc2[0][0] = ffma2(pd, v2.x, acc2[0][0]);
            acc2[0][1] = ffma2(pd, v2.y, acc2[0][1]);
            pd = pk2(p4.y, p4.y);
            acc2[1][0] = ffma2(pd, v2.x, acc2[1][0]);
            acc2[1][1] = ffma2(pd, v2.y, acc2[1][1]);
            pd = pk2(p4.z, p4.z);
            acc2[2][0] = ffma2(pd, v2.x, acc2[2][0]);
            acc2[2][1] = ffma2(pd, v2.y, acc2[2][1]);
            pd = pk2(p4.w, p4.w);
            acc2[3][0] = ffma2(pd, v2.x, acc2[3][0]);
            acc2[3][1] = ffma2(pd, v2.y, acc2[3][1]);
        }
    }

#pragma unroll
    for (int qi = 0; qi < 4; qi++) {
        float inv = 1.0f / l[qi];
        float x0, x1, x2, x3;
        up2(acc2[qi][0], x0, x1);
        up2(acc2[qi][1], x2, x3);
        const size_t orow = (size_t)(b * Tc + m0 + q0 + qi) * Cc + (h << 6) + (kg << 2);
        *(float4*)&Y[orow] = make_float4(x0 * inv, x1 * inv, x2 * inv, x3 * inv);
    }
}

// ============================================================================
extern "C" void kernel_launch(void* const* d_in, const int* in_sizes, int n_in,
                              void* d_out, int out_size)
{
    const float* x  = (const float*)d_in[0];
    const float* Wk = (const float*)d_in[1];
    const float* bk = (const float*)d_in[2];
    const float* Wq = (const float*)d_in[3];
    const float* bq = (const float*)d_in[4];
    const float* Wv = (const float*)d_in[5];
    const float* bv = (const float*)d_in[6];
    const float* Wp = (const float*)d_in[7];
    const float* bp = (const float*)d_in[8];
    float* out = (float*)d_out;

    float *pq, *pk, *pv, *py;
    cudaGetSymbolAddress((void**)&pq, g_q);
    cudaGetSymbolAddress((void**)&pk, g_k);
    cudaGetSymbolAddress((void**)&pv, g_v);
    cudaGetSymbolAddress((void**)&py, g_y);

    cudaFuncSetAttribute(flash_attn, cudaFuncAttributeMaxDynamicSharedMemorySize, FSMEM_BYTES);

    const int M = Bc * Tc, N = Cc, K = Cc;

    dim3 gg(N / GBN, M / GBM);   // (8, 32)
    gemm_nt<0><<<gg, 256>>>(x, Wq, bq, pq, M, N, K);
    gemm_nt<0><<<gg, 256>>>(x, Wk, bk, pk, M, N, K);
    gemm_nt<0><<<gg, 256>>>(x, Wv, bv, pv, M, N, K);

    dim3 fg(Tc / 64, Bc * Hc);   // (32, 32)
    flash_attn<<<fg, 256, FSMEM_BYTES>>>(pq, pk, pv, py);

    gemm_nt<1><<<gg, 256>>>(py, Wp, bp, out, M, N, K);
}

// round 9
// speedup vs baseline: 1.6250x; 1.6250x over previous
#include <cuda_runtime.h>
#include <cuda_fp16.h>
#include <cstdint>

#define Bc 2
#define Tc 2048
#define Cc 1024
#define Hc 16
#define Dc 64

__device__ float g_q[Bc * Hc * Tc * Dc];
__device__ float g_k[Bc * Hc * Tc * Dc];
__device__ float g_v[Bc * Hc * Tc * Dc];
__device__ float g_y[Bc * Tc * Cc];

// ---------------- packed f32x2 helpers ----------------
typedef unsigned long long u64t;
__device__ __forceinline__ u64t ffma2(u64t a, u64t b, u64t c) {
    u64t d; asm("fma.rn.f32x2 %0, %1, %2, %3;" : "=l"(d) : "l"(a), "l"(b), "l"(c)); return d;
}
__device__ __forceinline__ u64t pk2(float x, float y) {
    u64t r; asm("mov.b64 %0, {%1, %2};" : "=l"(r) : "f"(x), "f"(y)); return r;
}
__device__ __forceinline__ void up2(u64t v, float& x, float& y) {
    asm("mov.b64 {%0, %1}, %2;" : "=f"(x), "=f"(y) : "l"(v));
}

__device__ __forceinline__ uint32_t smem_u32(const void* p) {
    uint32_t a;
    asm("{ .reg .u64 t; cvta.to.shared.u64 t, %1; cvt.u32.u64 %0, t; }" : "=r"(a) : "l"(p));
    return a;
}
__device__ __forceinline__ void ldsm_x4(uint32_t addr, uint32_t& d0, uint32_t& d1,
                                        uint32_t& d2, uint32_t& d3) {
    asm volatile("ldmatrix.sync.aligned.m8n8.x4.shared.b16 {%0,%1,%2,%3}, [%4];"
                 : "=r"(d0), "=r"(d1), "=r"(d2), "=r"(d3) : "r"(addr));
}
__device__ __forceinline__ void ldsm_x4_t(uint32_t addr, uint32_t& d0, uint32_t& d1,
                                          uint32_t& d2, uint32_t& d3) {
    asm volatile("ldmatrix.sync.aligned.m8n8.x4.trans.shared.b16 {%0,%1,%2,%3}, [%4];"
                 : "=r"(d0), "=r"(d1), "=r"(d2), "=r"(d3) : "r"(addr));
}
__device__ __forceinline__ void mma_f16(float* c, const uint32_t* a, uint32_t b0, uint32_t b1) {
    asm volatile("mma.sync.aligned.m16n8k16.row.col.f32.f16.f16.f32 "
                 "{%0,%1,%2,%3}, {%4,%5,%6,%7}, {%8,%9}, {%0,%1,%2,%3};"
                 : "+f"(c[0]), "+f"(c[1]), "+f"(c[2]), "+f"(c[3])
                 : "r"(a[0]), "r"(a[1]), "r"(a[2]), "r"(a[3]), "r"(b0), "r"(b1));
}
__device__ __forceinline__ uint32_t pkh2(float x, float y) {
    __half2 h = __floats2half2_rn(x, y);
    return *reinterpret_cast<uint32_t*>(&h);
}
__device__ __forceinline__ uint4 cvt8h(float4 f0, float4 f1, float sc) {
    uint4 u;
    u.x = pkh2(f0.x * sc, f0.y * sc);
    u.y = pkh2(f0.z * sc, f0.w * sc);
    u.z = pkh2(f1.x * sc, f1.y * sc);
    u.w = pkh2(f1.z * sc, f1.w * sc);
    return u;
}

// ============================================================================
// NT GEMM (verbatim from the validated 1647us round): fp32 f32x2-packed FMA,
// CTA 128x128, K chunk 16, single-buffer + register prefetch.
// ============================================================================
#define GBM 128
#define GBN 128
#define GBK 16

template <int MODE>
__global__ void __launch_bounds__(256)
gemm_nt(const float* __restrict__ A, const float* __restrict__ B,
        const float* __restrict__ bias, float* __restrict__ C,
        int M, int N, int K)
{
    __shared__ __align__(16) float As[GBK][GBM];
    __shared__ __align__(16) float Bs[GBK][GBN];

    const int tid = threadIdx.x;
    const int m0 = blockIdx.y * GBM;
    const int n0 = blockIdx.x * GBN;
    const int row = (tid >> 4) << 3;
    const int col = (tid & 15) << 3;

    u64t acc2[8][4];
#pragma unroll
    for (int i = 0; i < 8; i++)
#pragma unroll
        for (int j = 0; j < 4; j++) acc2[i][j] = 0ull;

    float4 ra[2], rb[2];
#pragma unroll
    for (int it = 0; it < 2; it++) {
        int e = tid + it * 256;
        int r = e >> 2, c4 = (e & 3) << 2;
        ra[it] = *reinterpret_cast<const float4*>(&A[(size_t)(m0 + r) * K + c4]);
        rb[it] = *reinterpret_cast<const float4*>(&B[(size_t)(n0 + r) * K + c4]);
    }

    for (int k0 = 0; k0 < K; k0 += GBK) {
#pragma unroll
        for (int it = 0; it < 2; it++) {
            int e = tid + it * 256;
            int r = e >> 2, c4 = (e & 3) << 2;
            As[c4 + 0][r] = ra[it].x; As[c4 + 1][r] = ra[it].y;
            As[c4 + 2][r] = ra[it].z; As[c4 + 3][r] = ra[it].w;
            Bs[c4 + 0][r] = rb[it].x; Bs[c4 + 1][r] = rb[it].y;
            Bs[c4 + 2][r] = rb[it].z; Bs[c4 + 3][r] = rb[it].w;
        }
        __syncthreads();

        if (k0 + GBK < K) {
#pragma unroll
            for (int it = 0; it < 2; it++) {
                int e = tid + it * 256;
                int r = e >> 2, c4 = (e & 3) << 2;
                ra[it] = *reinterpret_cast<const float4*>(&A[(size_t)(m0 + r) * K + k0 + GBK + c4]);
                rb[it] = *reinterpret_cast<const float4*>(&B[(size_t)(n0 + r) * K + k0 + GBK + c4]);
            }
        }

#pragma unroll
        for (int k = 0; k < GBK; k++) {
            float a[8];
            *reinterpret_cast<float4*>(&a[0]) = *reinterpret_cast<const float4*>(&As[k][row]);
            *reinterpret_cast<float4*>(&a[4]) = *reinterpret_cast<const float4*>(&As[k][row + 4]);
            ulonglong2 b01 = *reinterpret_cast<const ulonglong2*>(&Bs[k][col]);
            ulonglong2 b23 = *reinterpret_cast<const ulonglong2*>(&Bs[k][col + 4]);
            u64t bb[4] = {b01.x, b01.y, b23.x, b23.y};
#pragma unroll
            for (int i = 0; i < 8; i++) {
                u64t ad = pk2(a[i], a[i]);
#pragma unroll
                for (int j = 0; j < 4; j++) acc2[i][j] = ffma2(ad, bb[j], acc2[i][j]);
            }
        }
        __syncthreads();
    }

#pragma unroll
    for (int i = 0; i < 8; i++) {
        int m = m0 + row + i;
        float v[8];
#pragma unroll
        for (int j = 0; j < 4; j++) up2(acc2[i][j], v[2 * j], v[2 * j + 1]);
#pragma unroll
        for (int j = 0; j < 8; j++) {
            int n = n0 + col + j;
            float val = v[j] + bias[n];
            if (MODE == 0) {
                int bb = m >> 11, tt = m & 2047, hh = n >> 6, dd = n & 63;
                C[((size_t)((bb * Hc + hh) * Tc + tt) << 6) + dd] = val;
            } else {
                C[(size_t)m * N + n] = val;
            }
        }
    }
}

// ============================================================================
// Flash attention via fp16 mma.sync (HMMA), fp32 accum. Causal.
// CTA: 128 q-rows x 64 kv per tile, 8 warps x 16 q-rows. D=64.
// S = Q@K^T (fp16 in, fp32 acc) -> warp-local softmax -> P stays in registers
// as fp16 A-fragments -> O += P@V^T-frags (ldmatrix.trans).
// Smem: fp16 tiles, 128B rows, 16B-block swizzle cb ^= (row&7).
// ============================================================================
__global__ void __launch_bounds__(256)
flash_attn(const float* __restrict__ Q, const float* __restrict__ K,
           const float* __restrict__ V, float* __restrict__ Y)
{
    __shared__ __align__(16) __half Qs[128 * 64];
    __shared__ __align__(16) __half Ks[64 * 64];
    __shared__ __align__(16) __half Vs[64 * 64];

    const int bh   = blockIdx.y;
    const int b    = bh >> 4;
    const int h    = bh & 15;
    const int qt   = gridDim.x - 1 - blockIdx.x;   // longest first
    const int m0   = qt << 7;
    const int tid  = threadIdx.x;
    const int lane = tid & 31;
    const int wq   = tid >> 5;
    const int mw   = m0 + (wq << 4);               // warp's first q row
    const size_t base = (size_t)bh * Tc * Dc;
    const float cQ = 0.125f * 1.4426950408889634f; // 1/sqrt(D) * log2(e)

    const uint32_t qsb = smem_u32(Qs);
    const uint32_t ksb = smem_u32(Ks);
    const uint32_t vsb = smem_u32(Vs);

    // ---- load Q tile: fp32 -> fp16 (scaled), swizzled ----
#pragma unroll
    for (int it = 0; it < 4; it++) {
        int e = tid + (it << 8);            // 0..1023 blocks of 8 halfs
        int row = e >> 3, cb = e & 7;
        const float4* src = (const float4*)&Q[base + (size_t)(m0 + row) * Dc + (cb << 3)];
        *(uint4*)&Qs[(row << 6) + ((cb ^ (row & 7)) << 3)] = cvt8h(src[0], src[1], cQ);
    }
    __syncthreads();

    // ---- Q fragments (held in registers for the whole kernel) ----
    uint32_t qf[4][4];
    {
        int rowq = (wq << 4) + (lane & 7) + (((lane >> 3) & 1) << 3);
#pragma unroll
        for (int ks = 0; ks < 4; ks++) {
            int cb = (ks << 1) + (lane >> 4);
            ldsm_x4(qsb + (rowq << 7) + ((cb ^ (rowq & 7)) << 4),
                    qf[ks][0], qf[ks][1], qf[ks][2], qf[ks][3]);
        }
    }

    // per-thread address components
    const int rowk_b = (lane & 7) + ((lane >> 4) << 3);          // + ntp*16
    const int cbk_b  = (lane >> 3) & 1;                          // + 2*ks
    const int rowv_b = (lane & 7) + (((lane >> 3) & 1) << 3);    // + kvs*16
    const int cbv_b  = (lane >> 4);                              // + 2*ntp

    float oacc[8][4];
#pragma unroll
    for (int i = 0; i < 8; i++)
#pragma unroll
        for (int j = 0; j < 4; j++) oacc[i][j] = 0.f;
    float mrow0 = -1e30f, mrow1 = -1e30f, lrow0 = 0.f, lrow1 = 0.f;

    const int nkv = (qt << 1) + 2;
    for (int j = 0; j < nkv; j++) {
        const int n0 = j << 6;
        __syncthreads();
#pragma unroll
        for (int it = 0; it < 2; it++) {
            int e = tid + (it << 8);        // 0..511 blocks
            int row = e >> 3, cb = e & 7;
            int dsth = (row << 6) + ((cb ^ (row & 7)) << 3);
            const float4* sk = (const float4*)&K[base + (size_t)(n0 + row) * Dc + (cb << 3)];
            *(uint4*)&Ks[dsth] = cvt8h(sk[0], sk[1], 1.0f);
            const float4* sv = (const float4*)&V[base + (size_t)(n0 + row) * Dc + (cb << 3)];
            *(uint4*)&Vs[dsth] = cvt8h(sv[0], sv[1], 1.0f);
        }
        __syncthreads();

        if (n0 <= mw + 15) {                // warp has unmasked work this tile
            // ---- S = Q @ K^T ----
            float sacc[8][4];
#pragma unroll
            for (int i = 0; i < 8; i++)
#pragma unroll
                for (int q = 0; q < 4; q++) sacc[i][q] = 0.f;
#pragma unroll
            for (int ks = 0; ks < 4; ks++) {
#pragma unroll
                for (int ntp = 0; ntp < 4; ntp++) {
                    int rowk = (ntp << 4) + rowk_b;
                    int cbk = (ks << 1) + cbk_b;
                    uint32_t b0, b1, b2, b3;
                    ldsm_x4(ksb + (rowk << 7) + ((cbk ^ (rowk & 7)) << 4), b0, b1, b2, b3);
                    mma_f16(sacc[2 * ntp],     qf[ks], b0, b1);
                    mma_f16(sacc[2 * ntp + 1], qf[ks], b2, b3);
                }
            }

            // ---- causal mask (diagonal-overlap tiles only) ----
            if (n0 + 63 > mw) {
                int mA = mw + (lane >> 2), mB = mA + 8;
#pragma unroll
                for (int nt = 0; nt < 8; nt++) {
                    int n = n0 + (nt << 3) + ((lane & 3) << 1);
                    if (n     > mA) sacc[nt][0] = -1e30f;
                    if (n + 1 > mA) sacc[nt][1] = -1e30f;
                    if (n     > mB) sacc[nt][2] = -1e30f;
                    if (n + 1 > mB) sacc[nt][3] = -1e30f;
                }
            }

            // ---- online softmax (rows rA = lane>>2, rB = rA+8; base 2) ----
            float mx0 = -1e30f, mx1 = -1e30f;
#pragma unroll
            for (int nt = 0; nt < 8; nt++) {
                mx0 = fmaxf(mx0, fmaxf(sacc[nt][0], sacc[nt][1]));
                mx1 = fmaxf(mx1, fmaxf(sacc[nt][2], sacc[nt][3]));
            }
            mx0 = fmaxf(mx0, __shfl_xor_sync(0xffffffffu, mx0, 1));
            mx0 = fmaxf(mx0, __shfl_xor_sync(0xffffffffu, mx0, 2));
            mx1 = fmaxf(mx1, __shfl_xor_sync(0xffffffffu, mx1, 1));
            mx1 = fmaxf(mx1, __shfl_xor_sync(0xffffffffu, mx1, 2));
            float mn0 = fmaxf(mrow0, mx0), mn1 = fmaxf(mrow1, mx1);
            float a0 = exp2f(mrow0 - mn0), a1 = exp2f(mrow1 - mn1);
            mrow0 = mn0; mrow1 = mn1;
            float s0 = 0.f, s1 = 0.f;
#pragma unroll
            for (int nt = 0; nt < 8; nt++) {
                sacc[nt][0] = exp2f(sacc[nt][0] - mn0);
                sacc[nt][1] = exp2f(sacc[nt][1] - mn0);
                sacc[nt][2] = exp2f(sacc[nt][2] - mn1);
                sacc[nt][3] = exp2f(sacc[nt][3] - mn1);
                s0 += sacc[nt][0] + sacc[nt][1];
                s1 += sacc[nt][2] + sacc[nt][3];
            }
            s0 += __shfl_xor_sync(0xffffffffu, s0, 1);
            s0 += __shfl_xor_sync(0xffffffffu, s0, 2);
            s1 += __shfl_xor_sync(0xffffffffu, s1, 1);
            s1 += __shfl_xor_sync(0xffffffffu, s1, 2);
            lrow0 = lrow0 * a0 + s0;
            lrow1 = lrow1 * a1 + s1;
#pragma unroll
            for (int nt = 0; nt < 8; nt++) {
                oacc[nt][0] *= a0; oacc[nt][1] *= a0;
                oacc[nt][2] *= a1; oacc[nt][3] *= a1;
            }

            // ---- P -> fp16 A-fragments (register-resident, no smem) ----
            uint32_t pp[4][4];
#pragma unroll
            for (int kvs = 0; kvs < 4; kvs++) {
                pp[kvs][0] = pkh2(sacc[2 * kvs][0],     sacc[2 * kvs][1]);
                pp[kvs][1] = pkh2(sacc[2 * kvs][2],     sacc[2 * kvs][3]);
                pp[kvs][2] = pkh2(sacc[2 * kvs + 1][0], sacc[2 * kvs + 1][1]);
                pp[kvs][3] = pkh2(sacc[2 * kvs + 1][2], sacc[2 * kvs + 1][3]);
            }

            // ---- O += P @ V (V^T fragments via ldmatrix.trans) ----
#pragma unroll
            for (int kvs = 0; kvs < 4; kvs++) {
                int rowv = (kvs << 4) + rowv_b;
#pragma unroll
                for (int ntp = 0; ntp < 4; ntp++) {
                    int cbv = (ntp << 1) + cbv_b;
                    uint32_t b0, b1, b2, b3;
                    ldsm_x4_t(vsb + (rowv << 7) + ((cbv ^ (rowv & 7)) << 4), b0, b1, b2, b3);
                    mma_f16(oacc[2 * ntp],     pp[kvs], b0, b1);
                    mma_f16(oacc[2 * ntp + 1], pp[kvs], b2, b3);
                }
            }
        }
    }

    // ---- normalize + write fp32 [B,T,C] head slice ----
    float inv0 = 1.0f / lrow0, inv1 = 1.0f / lrow1;
    int mA = mw + (lane >> 2);
    size_t r0 = (size_t)(b * Tc + mA) * Cc + (h << 6) + ((lane & 3) << 1);
    size_t r1 = r0 + (size_t)8 * Cc;
#pragma unroll
    for (int nt = 0; nt < 8; nt++) {
        *(float2*)&Y[r0 + (nt << 3)] = make_float2(oacc[nt][0] * inv0, oacc[nt][1] * inv0);
        *(float2*)&Y[r1 + (nt << 3)] = make_float2(oacc[nt][2] * inv1, oacc[nt][3] * inv1);
    }
}

// ============================================================================
extern "C" void kernel_launch(void* const* d_in, const int* in_sizes, int n_in,
                              void* d_out, int out_size)
{
    const float* x  = (const float*)d_in[0];
    const float* Wk = (const float*)d_in[1];
    const float* bk = (const float*)d_in[2];
    const float* Wq = (const float*)d_in[3];
    const float* bq = (const float*)d_in[4];
    const float* Wv = (const float*)d_in[5];
    const float* bv = (const float*)d_in[6];
    const float* Wp = (const float*)d_in[7];
    const float* bp = (const float*)d_in[8];
    float* out = (float*)d_out;

    float *pq, *pk, *pv, *py;
    cudaGetSymbolAddress((void**)&pq, g_q);
    cudaGetSymbolAddress((void**)&pk, g_k);
    cudaGetSymbolAddress((void**)&pv, g_v);
    cudaGetSymbolAddress((void**)&py, g_y);

    const int M = Bc * Tc, N = Cc, K = Cc;

    dim3 gg(N / GBN, M / GBM);      // (8, 32)
    gemm_nt<0><<<gg, 256>>>(x, Wq, bq, pq, M, N, K);
    gemm_nt<0><<<gg, 256>>>(x, Wk, bk, pk, M, N, K);
    gemm_nt<0><<<gg, 256>>>(x, Wv, bv, pv, M, N, K);

    dim3 fg(Tc / 128, Bc * Hc);     // (16, 32)
    flash_attn<<<fg, 256>>>(pq, pk, pv, py);

    gemm_nt<1><<<gg, 256>>>(py, Wp, bp, out, M, N, K);
}

// round 10
// speedup vs baseline: 7.6317x; 4.6965x over previous
#include <cuda_runtime.h>
#include <cuda_fp16.h>
#include <cstdint>

#define Bc 2
#define Tc 2048
#define Cc 1024
#define Hc 16
#define Dc 64
#define Mtot (Bc * Tc)

// fp16 staging buffers
__device__ __half g_xh[Mtot * Cc];
__device__ __half g_wqh[Cc * Cc];
__device__ __half g_wkh[Cc * Cc];
__device__ __half g_wvh[Cc * Cc];
__device__ __half g_wph[Cc * Cc];
__device__ __half g_qh[Bc * Hc * Tc * Dc];
__device__ __half g_kh[Bc * Hc * Tc * Dc];
__device__ __half g_vh[Bc * Hc * Tc * Dc];
__device__ __half g_yh[Mtot * Cc];

// ============================ PTX helpers ============================
__device__ __forceinline__ uint32_t smem_u32(const void* p) {
    uint32_t a;
    asm("{ .reg .u64 t; cvta.to.shared.u64 t, %1; cvt.u32.u64 %0, t; }" : "=r"(a) : "l"(p));
    return a;
}
__device__ __forceinline__ void ldsm_x4(uint32_t addr, uint32_t& d0, uint32_t& d1,
                                        uint32_t& d2, uint32_t& d3) {
    asm volatile("ldmatrix.sync.aligned.m8n8.x4.shared.b16 {%0,%1,%2,%3}, [%4];"
                 : "=r"(d0), "=r"(d1), "=r"(d2), "=r"(d3) : "r"(addr));
}
__device__ __forceinline__ void ldsm_x4_t(uint32_t addr, uint32_t& d0, uint32_t& d1,
                                          uint32_t& d2, uint32_t& d3) {
    asm volatile("ldmatrix.sync.aligned.m8n8.x4.trans.shared.b16 {%0,%1,%2,%3}, [%4];"
                 : "=r"(d0), "=r"(d1), "=r"(d2), "=r"(d3) : "r"(addr));
}
__device__ __forceinline__ void mma_f16(float* c, const uint32_t* a, uint32_t b0, uint32_t b1) {
    asm volatile("mma.sync.aligned.m16n8k16.row.col.f32.f16.f16.f32 "
                 "{%0,%1,%2,%3}, {%4,%5,%6,%7}, {%8,%9}, {%0,%1,%2,%3};"
                 : "+f"(c[0]), "+f"(c[1]), "+f"(c[2]), "+f"(c[3])
                 : "r"(a[0]), "r"(a[1]), "r"(a[2]), "r"(a[3]), "r"(b0), "r"(b1));
}
__device__ __forceinline__ uint32_t pkh2(float x, float y) {
    __half2 h = __floats2half2_rn(x, y);
    return *reinterpret_cast<uint32_t*>(&h);
}
__device__ __forceinline__ void cpasync16(uint32_t dst, const void* src) {
    asm volatile("cp.async.cg.shared.global [%0], [%1], 16;" :: "r"(dst), "l"(src));
}
#define CPCOMMIT() asm volatile("cp.async.commit_group;" ::: "memory")
#define CPWAIT(n)  asm volatile("cp.async.wait_group %0;" :: "n"(n) : "memory")

// ============================================================================
// fp32 -> fp16 convert (grid-stride over float4)
// ============================================================================
__global__ void cvt_h(const float* __restrict__ in, __half* __restrict__ out, int n4)
{
    int i = blockIdx.x * blockDim.x + threadIdx.x;
    if (i < n4) {
        float4 v = reinterpret_cast<const float4*>(in)[i];
        __half2* o = reinterpret_cast<__half2*>(out) + 2 * i;
        o[0] = __floats2half2_rn(v.x, v.y);
        o[1] = __floats2half2_rn(v.z, v.w);
    }
}

// ============================================================================
// fp16 HMMA NT GEMM: C[m,n] = sum_k A[m,k]*B[n,k] + bias[n]
// A,B fp16 K-major. CTA 128x128, 8 warps (warp tile 64x32), K-chunk 64,
// 3-stage cp.async pipeline. Fragment index math identical to the validated
// flash S=QK^T pattern (A = Q-frags, B = K-frags).
// MODE 0: fp16 out, scatter to [B,H,T,D]. MODE 1: fp32 out, row-major [M,N].
// ============================================================================
#define GSTAGE 32768           // Ah 16KB + Bh 16KB per stage
#define GSMEM  (3 * GSTAGE)    // 96KB

__device__ __forceinline__ void gemm_issue(uint32_t sA, uint32_t sB,
                                           const __half* __restrict__ A,
                                           const __half* __restrict__ B,
                                           int m0, int n0, int k0, int tid)
{
#pragma unroll
    for (int it = 0; it < 4; it++) {
        int e = tid + (it << 8);
        int row = e >> 3, cb = e & 7;
        uint32_t off = (uint32_t)(row * 128 + ((cb ^ (row & 7)) << 4));
        cpasync16(sA + off, A + (size_t)(m0 + row) * Cc + k0 + (cb << 3));
        cpasync16(sB + off, B + (size_t)(n0 + row) * Cc + k0 + (cb << 3));
    }
}

template <int MODE>
__global__ void __launch_bounds__(256)
gemm_h(const __half* __restrict__ A, const __half* __restrict__ B,
       const float* __restrict__ bias, void* __restrict__ Cout)
{
    extern __shared__ __align__(16) char gsm[];
    const uint32_t sb = smem_u32(gsm);

    const int tid  = threadIdx.x;
    const int lane = tid & 31;
    const int wid  = tid >> 5;
    const int wm   = (wid >> 2) << 6;   // 0 / 64
    const int wn   = (wid & 3) << 5;    // 0,32,64,96
    const int m0   = blockIdx.y << 7;
    const int n0   = blockIdx.x << 7;

    // per-lane fragment address components (identical to flash Q/K patterns)
    const int rowa_l = (lane & 7) + (((lane >> 3) & 1) << 3);
    const int cba_l  = lane >> 4;
    const int rowb_l = (lane & 7) + ((lane >> 4) << 3);
    const int cbb_l  = (lane >> 3) & 1;

    float c[4][4][4];
#pragma unroll
    for (int i = 0; i < 4; i++)
#pragma unroll
        for (int j = 0; j < 4; j++)
#pragma unroll
            for (int q = 0; q < 4; q++) c[i][j][q] = 0.f;

    const int nch = Cc / 64;   // 16

    // prologue: stages 0,1
    gemm_issue(sb, sb + 16384, A, B, m0, n0, 0, tid);
    CPCOMMIT();
    gemm_issue(sb + GSTAGE, sb + GSTAGE + 16384, A, B, m0, n0, 64, tid);
    CPCOMMIT();

    for (int ch = 0; ch < nch; ch++) {
        if (ch + 1 < nch) { CPWAIT(1); } else { CPWAIT(0); }
        __syncthreads();
        if (ch + 2 < nch) {
            uint32_t st = sb + (uint32_t)((ch + 2) % 3) * GSTAGE;
            gemm_issue(st, st + 16384, A, B, m0, n0, (ch + 2) << 6, tid);
            CPCOMMIT();
        }

        const uint32_t sA = sb + (uint32_t)(ch % 3) * GSTAGE;
        const uint32_t sB = sA + 16384;

#pragma unroll
        for (int ks = 0; ks < 4; ks++) {
            // B fragments: 32 n-rows = 2 x ldsm_x4
            uint32_t bf[8];
#pragma unroll
            for (int ntp = 0; ntp < 2; ntp++) {
                int rowb = wn + (ntp << 4) + rowb_l;
                int cbb = (ks << 1) + cbb_l;
                ldsm_x4(sB + (rowb << 7) + ((cbb ^ (rowb & 7)) << 4),
                        bf[4 * ntp], bf[4 * ntp + 1], bf[4 * ntp + 2], bf[4 * ntp + 3]);
            }
#pragma unroll
            for (int mt = 0; mt < 4; mt++) {
                int rowa = wm + (mt << 4) + rowa_l;
                int cba = (ks << 1) + cba_l;
                uint32_t af[4];
                ldsm_x4(sA + (rowa << 7) + ((cba ^ (rowa & 7)) << 4),
                        af[0], af[1], af[2], af[3]);
#pragma unroll
                for (int ntp = 0; ntp < 2; ntp++) {
                    mma_f16(c[mt][2 * ntp],     af, bf[4 * ntp],     bf[4 * ntp + 1]);
                    mma_f16(c[mt][2 * ntp + 1], af, bf[4 * ntp + 2], bf[4 * ntp + 3]);
                }
            }
        }
        __syncthreads();
    }

    // epilogue: frag (m,n): m = base + lane>>2 (+8 for regs 2,3), n = +2*(lane&3)
#pragma unroll
    for (int mt = 0; mt < 4; mt++) {
#pragma unroll
        for (int n8 = 0; n8 < 4; n8++) {
            int m = m0 + wm + (mt << 4) + (lane >> 2);
            int n = n0 + wn + (n8 << 3) + ((lane & 3) << 1);
            float b0 = bias[n], b1 = bias[n + 1];
            float v00 = c[mt][n8][0] + b0, v01 = c[mt][n8][1] + b1;
            float v10 = c[mt][n8][2] + b0, v11 = c[mt][n8][3] + b1;
            if (MODE == 0) {
                __half* Ch = (__half*)Cout;
                int hh = n >> 6, dd = n & 63;
                int bb = m >> 11, tt = m & 2047;
                size_t d0 = ((size_t)((bb * Hc + hh) * Tc + tt) << 6) + dd;
                int m2 = m + 8;
                int bb2 = m2 >> 11, tt2 = m2 & 2047;
                size_t d1 = ((size_t)((bb2 * Hc + hh) * Tc + tt2) << 6) + dd;
                *(__half2*)&Ch[d0] = __floats2half2_rn(v00, v01);
                *(__half2*)&Ch[d1] = __floats2half2_rn(v10, v11);
            } else {
                float* Cf = (float*)Cout;
                *(float2*)&Cf[(size_t)m * Cc + n]       = make_float2(v00, v01);
                *(float2*)&Cf[(size_t)(m + 8) * Cc + n] = make_float2(v10, v11);
            }
        }
    }
}

// ============================================================================
// Flash attention via fp16 mma.sync, fp32 accum. Causal. fp16 in, fp16 out.
// CTA: 128 q x 64 kv, 8 warps x 16 q. Softmax scale applied in fp32 on S.
// ============================================================================
__global__ void __launch_bounds__(256)
flash_attn(const __half* __restrict__ Q, const __half* __restrict__ K,
           const __half* __restrict__ V, __half* __restrict__ Y)
{
    __shared__ __align__(16) __half Qs[128 * 64];
    __shared__ __align__(16) __half Ks[64 * 64];
    __shared__ __align__(16) __half Vs[64 * 64];

    const int bh   = blockIdx.y;
    const int b    = bh >> 4;
    const int h    = bh & 15;
    const int qt   = gridDim.x - 1 - blockIdx.x;
    const int m0   = qt << 7;
    const int tid  = threadIdx.x;
    const int lane = tid & 31;
    const int wq   = tid >> 5;
    const int mw   = m0 + (wq << 4);
    const size_t base = (size_t)bh * Tc * Dc;
    const float cS = 0.125f * 1.4426950408889634f;   // 1/sqrt(D) * log2(e)

    const uint32_t qsb = smem_u32(Qs);
    const uint32_t ksb = smem_u32(Ks);
    const uint32_t vsb = smem_u32(Vs);

    // Q tile (fp16 gmem -> swizzled smem)
#pragma unroll
    for (int it = 0; it < 4; it++) {
        int e = tid + (it << 8);
        int row = e >> 3, cb = e & 7;
        *(uint4*)&Qs[(row << 6) + ((cb ^ (row & 7)) << 3)] =
            *(const uint4*)&Q[base + (size_t)(m0 + row) * Dc + (cb << 3)];
    }
    __syncthreads();

    uint32_t qf[4][4];
    {
        int rowq = (wq << 4) + (lane & 7) + (((lane >> 3) & 1) << 3);
#pragma unroll
        for (int ks = 0; ks < 4; ks++) {
            int cb = (ks << 1) + (lane >> 4);
            ldsm_x4(qsb + (rowq << 7) + ((cb ^ (rowq & 7)) << 4),
                    qf[ks][0], qf[ks][1], qf[ks][2], qf[ks][3]);
        }
    }

    const int rowk_b = (lane & 7) + ((lane >> 4) << 3);
    const int cbk_b  = (lane >> 3) & 1;
    const int rowv_b = (lane & 7) + (((lane >> 3) & 1) << 3);
    const int cbv_b  = (lane >> 4);

    float oacc[8][4];
#pragma unroll
    for (int i = 0; i < 8; i++)
#pragma unroll
        for (int j = 0; j < 4; j++) oacc[i][j] = 0.f;
    float mrow0 = -1e30f, mrow1 = -1e30f, lrow0 = 0.f, lrow1 = 0.f;

    const int nkv = (qt << 1) + 2;
    for (int j = 0; j < nkv; j++) {
        const int n0 = j << 6;
        __syncthreads();
#pragma unroll
        for (int it = 0; it < 2; it++) {
            int e = tid + (it << 8);
            int row = e >> 3, cb = e & 7;
            int dsth = (row << 6) + ((cb ^ (row & 7)) << 3);
            *(uint4*)&Ks[dsth] = *(const uint4*)&K[base + (size_t)(n0 + row) * Dc + (cb << 3)];
            *(uint4*)&Vs[dsth] = *(const uint4*)&V[base + (size_t)(n0 + row) * Dc + (cb << 3)];
        }
        __syncthreads();

        if (n0 <= mw + 15) {
            float sacc[8][4];
#pragma unroll
            for (int i = 0; i < 8; i++)
#pragma unroll
                for (int q = 0; q < 4; q++) sacc[i][q] = 0.f;
#pragma unroll
            for (int ks = 0; ks < 4; ks++) {
#pragma unroll
                for (int ntp = 0; ntp < 4; ntp++) {
                    int rowk = (ntp << 4) + rowk_b;
                    int cbk = (ks << 1) + cbk_b;
                    uint32_t b0, b1, b2, b3;
                    ldsm_x4(ksb + (rowk << 7) + ((cbk ^ (rowk & 7)) << 4), b0, b1, b2, b3);
                    mma_f16(sacc[2 * ntp],     qf[ks], b0, b1);
                    mma_f16(sacc[2 * ntp + 1], qf[ks], b2, b3);
                }
            }
            // fp32 softmax scale (exact; also folds log2e for exp2)
#pragma unroll
            for (int nt = 0; nt < 8; nt++) {
                sacc[nt][0] *= cS; sacc[nt][1] *= cS;
                sacc[nt][2] *= cS; sacc[nt][3] *= cS;
            }

            if (n0 + 63 > mw) {
                int mA = mw + (lane >> 2), mB = mA + 8;
#pragma unroll
                for (int nt = 0; nt < 8; nt++) {
                    int n = n0 + (nt << 3) + ((lane & 3) << 1);
                    if (n     > mA) sacc[nt][0] = -1e30f;
                    if (n + 1 > mA) sacc[nt][1] = -1e30f;
                    if (n     > mB) sacc[nt][2] = -1e30f;
                    if (n + 1 > mB) sacc[nt][3] = -1e30f;
                }
            }

            float mx0 = -1e30f, mx1 = -1e30f;
#pragma unroll
            for (int nt = 0; nt < 8; nt++) {
                mx0 = fmaxf(mx0, fmaxf(sacc[nt][0], sacc[nt][1]));
                mx1 = fmaxf(mx1, fmaxf(sacc[nt][2], sacc[nt][3]));
            }
            mx0 = fmaxf(mx0, __shfl_xor_sync(0xffffffffu, mx0, 1));
            mx0 = fmaxf(mx0, __shfl_xor_sync(0xffffffffu, mx0, 2));
            mx1 = fmaxf(mx1, __shfl_xor_sync(0xffffffffu, mx1, 1));
            mx1 = fmaxf(mx1, __shfl_xor_sync(0xffffffffu, mx1, 2));
            float mn0 = fmaxf(mrow0, mx0), mn1 = fmaxf(mrow1, mx1);
            float a0 = exp2f(mrow0 - mn0), a1 = exp2f(mrow1 - mn1);
            mrow0 = mn0; mrow1 = mn1;
            float s0 = 0.f, s1 = 0.f;
#pragma unroll
            for (int nt = 0; nt < 8; nt++) {
                sacc[nt][0] = exp2f(sacc[nt][0] - mn0);
                sacc[nt][1] = exp2f(sacc[nt][1] - mn0);
                sacc[nt][2] = exp2f(sacc[nt][2] - mn1);
                sacc[nt][3] = exp2f(sacc[nt][3] - mn1);
                s0 += sacc[nt][0] + sacc[nt][1];
                s1 += sacc[nt][2] + sacc[nt][3];
            }
            s0 += __shfl_xor_sync(0xffffffffu, s0, 1);
            s0 += __shfl_xor_sync(0xffffffffu, s0, 2);
            s1 += __shfl_xor_sync(0xffffffffu, s1, 1);
            s1 += __shfl_xor_sync(0xffffffffu, s1, 2);
            lrow0 = lrow0 * a0 + s0;
            lrow1 = lrow1 * a1 + s1;
#pragma unroll
            for (int nt = 0; nt < 8; nt++) {
                oacc[nt][0] *= a0; oacc[nt][1] *= a0;
                oacc[nt][2] *= a1; oacc[nt][3] *= a1;
            }

            uint32_t pp[4][4];
#pragma unroll
            for (int kvs = 0; kvs < 4; kvs++) {
                pp[kvs][0] = pkh2(sacc[2 * kvs][0],     sacc[2 * kvs][1]);
                pp[kvs][1] = pkh2(sacc[2 * kvs][2],     sacc[2 * kvs][3]);
                pp[kvs][2] = pkh2(sacc[2 * kvs + 1][0], sacc[2 * kvs + 1][1]);
                pp[kvs][3] = pkh2(sacc[2 * kvs + 1][2], sacc[2 * kvs + 1][3]);
            }
#pragma unroll
            for (int kvs = 0; kvs < 4; kvs++) {
                int rowv = (kvs << 4) + rowv_b;
#pragma unroll
                for (int ntp = 0; ntp < 4; ntp++) {
                    int cbv = (ntp << 1) + cbv_b;
                    uint32_t b0, b1, b2, b3;
                    ldsm_x4_t(vsb + (rowv << 7) + ((cbv ^ (rowv & 7)) << 4), b0, b1, b2, b3);
                    mma_f16(oacc[2 * ntp],     pp[kvs], b0, b1);
                    mma_f16(oacc[2 * ntp + 1], pp[kvs], b2, b3);
                }
            }
        }
    }

    // normalize + write fp16 y [B,T,C] head slice
    float inv0 = 1.0f / lrow0, inv1 = 1.0f / lrow1;
    int mA = mw + (lane >> 2);
    size_t r0 = (size_t)(b * Tc + mA) * Cc + (h << 6) + ((lane & 3) << 1);
    size_t r1 = r0 + (size_t)8 * Cc;
#pragma unroll
    for (int nt = 0; nt < 8; nt++) {
        *(__half2*)&Y[r0 + (nt << 3)] = __floats2half2_rn(oacc[nt][0] * inv0, oacc[nt][1] * inv0);
        *(__half2*)&Y[r1 + (nt << 3)] = __floats2half2_rn(oacc[nt][2] * inv1, oacc[nt][3] * inv1);
    }
}

// ============================================================================
extern "C" void kernel_launch(void* const* d_in, const int* in_sizes, int n_in,
                              void* d_out, int out_size)
{
    const float* x  = (const float*)d_in[0];
    const float* Wk = (const float*)d_in[1];
    const float* bk = (const float*)d_in[2];
    const float* Wq = (const float*)d_in[3];
    const float* bq = (const float*)d_in[4];
    const float* Wv = (const float*)d_in[5];
    const float* bv = (const float*)d_in[6];
    const float* Wp = (const float*)d_in[7];
    const float* bp = (const float*)d_in[8];
    float* out = (float*)d_out;

    __half *xh, *wqh, *wkh, *wvh, *wph, *qh, *kh, *vh, *yh;
    cudaGetSymbolAddress((void**)&xh,  g_xh);
    cudaGetSymbolAddress((void**)&wqh, g_wqh);
    cudaGetSymbolAddress((void**)&wkh, g_wkh);
    cudaGetSymbolAddress((void**)&wvh, g_wvh);
    cudaGetSymbolAddress((void**)&wph, g_wph);
    cudaGetSymbolAddress((void**)&qh,  g_qh);
    cudaGetSymbolAddress((void**)&kh,  g_kh);
    cudaGetSymbolAddress((void**)&vh,  g_vh);
    cudaGetSymbolAddress((void**)&yh,  g_yh);

    cudaFuncSetAttribute(gemm_h<0>, cudaFuncAttributeMaxDynamicSharedMemorySize, GSMEM);
    cudaFuncSetAttribute(gemm_h<1>, cudaFuncAttributeMaxDynamicSharedMemorySize, GSMEM);

    // fp32 -> fp16 staging
    const int nx4 = (Mtot * Cc) / 4, nw4 = (Cc * Cc) / 4;
    cvt_h<<<(nx4 + 255) / 256, 256>>>(x,  xh,  nx4);
    cvt_h<<<(nw4 + 255) / 256, 256>>>(Wq, wqh, nw4);
    cvt_h<<<(nw4 + 255) / 256, 256>>>(Wk, wkh, nw4);
    cvt_h<<<(nw4 + 255) / 256, 256>>>(Wv, wvh, nw4);
    cvt_h<<<(nw4 + 255) / 256, 256>>>(Wp, wph, nw4);

    dim3 gg(Cc / 128, Mtot / 128);   // (8, 32)
    gemm_h<0><<<gg, 256, GSMEM>>>(xh, wqh, bq, qh);
    gemm_h<0><<<gg, 256, GSMEM>>>(xh, wkh, bk, kh);
    gemm_h<0><<<gg, 256, GSMEM>>>(xh, wvh, bv, vh);

    dim3 fg(Tc / 128, Bc * Hc);      // (16, 32)
    flash_attn<<<fg, 256>>>(qh, kh, vh, yh);

    gemm_h<1><<<gg, 256, GSMEM>>>(yh, wph, bp, out);
}

// round 11
// speedup vs baseline: 8.1373x; 1.0662x over previous
#include <cuda_runtime.h>
#include <cuda_fp16.h>
#include <cstdint>

#define Bc 2
#define Tc 2048
#define Cc 1024
#define Hc 16
#define Dc 64
#define Mtot (Bc * Tc)

// fp16 staging buffers
__device__ __half g_xh[Mtot * Cc];
__device__ __half g_wqh[Cc * Cc];
__device__ __half g_wkh[Cc * Cc];
__device__ __half g_wvh[Cc * Cc];
__device__ __half g_wph[Cc * Cc];
__device__ __half g_qh[Bc * Hc * Tc * Dc];
__device__ __half g_kh[Bc * Hc * Tc * Dc];
__device__ __half g_vh[Bc * Hc * Tc * Dc];
__device__ __half g_yh[Mtot * Cc];

// ============================ PTX helpers ============================
__device__ __forceinline__ uint32_t smem_u32(const void* p) {
    uint32_t a;
    asm("{ .reg .u64 t; cvta.to.shared.u64 t, %1; cvt.u32.u64 %0, t; }" : "=r"(a) : "l"(p));
    return a;
}
__device__ __forceinline__ void ldsm_x4(uint32_t addr, uint32_t& d0, uint32_t& d1,
                                        uint32_t& d2, uint32_t& d3) {
    asm volatile("ldmatrix.sync.aligned.m8n8.x4.shared.b16 {%0,%1,%2,%3}, [%4];"
                 : "=r"(d0), "=r"(d1), "=r"(d2), "=r"(d3) : "r"(addr));
}
__device__ __forceinline__ void ldsm_x4_t(uint32_t addr, uint32_t& d0, uint32_t& d1,
                                          uint32_t& d2, uint32_t& d3) {
    asm volatile("ldmatrix.sync.aligned.m8n8.x4.trans.shared.b16 {%0,%1,%2,%3}, [%4];"
                 : "=r"(d0), "=r"(d1), "=r"(d2), "=r"(d3) : "r"(addr));
}
__device__ __forceinline__ void mma_f16(float* c, const uint32_t* a, uint32_t b0, uint32_t b1) {
    asm volatile("mma.sync.aligned.m16n8k16.row.col.f32.f16.f16.f32 "
                 "{%0,%1,%2,%3}, {%4,%5,%6,%7}, {%8,%9}, {%0,%1,%2,%3};"
                 : "+f"(c[0]), "+f"(c[1]), "+f"(c[2]), "+f"(c[3])
                 : "r"(a[0]), "r"(a[1]), "r"(a[2]), "r"(a[3]), "r"(b0), "r"(b1));
}
__device__ __forceinline__ uint32_t pkh2(float x, float y) {
    __half2 h = __floats2half2_rn(x, y);
    return *reinterpret_cast<uint32_t*>(&h);
}
__device__ __forceinline__ void cpasync16(uint32_t dst, const void* src) {
    asm volatile("cp.async.cg.shared.global [%0], [%1], 16;" :: "r"(dst), "l"(src));
}
#define CPCOMMIT() asm volatile("cp.async.commit_group;" ::: "memory")
#define CPWAIT(n)  asm volatile("cp.async.wait_group %0;" :: "n"(n) : "memory")

// ============================================================================
// fp32 -> fp16 converts
// ============================================================================
__global__ void cvt_h(const float* __restrict__ in, __half* __restrict__ out, int n4)
{
    int i = blockIdx.x * blockDim.x + threadIdx.x;
    if (i < n4) {
        float4 v = reinterpret_cast<const float4*>(in)[i];
        __half2* o = reinterpret_cast<__half2*>(out) + 2 * i;
        o[0] = __floats2half2_rn(v.x, v.y);
        o[1] = __floats2half2_rn(v.z, v.w);
    }
}

__global__ void cvt_w4(const float* __restrict__ w0, const float* __restrict__ w1,
                       const float* __restrict__ w2, const float* __restrict__ w3,
                       __half* __restrict__ o0, __half* __restrict__ o1,
                       __half* __restrict__ o2, __half* __restrict__ o3)
{
    const float* src = (blockIdx.y == 0) ? w0 : (blockIdx.y == 1) ? w1
                     : (blockIdx.y == 2) ? w2 : w3;
    __half* dst = (blockIdx.y == 0) ? o0 : (blockIdx.y == 1) ? o1
                : (blockIdx.y == 2) ? o2 : o3;
    int i = blockIdx.x * blockDim.x + threadIdx.x;   // < 1024*1024/4
    float4 v = reinterpret_cast<const float4*>(src)[i];
    __half2* o = reinterpret_cast<__half2*>(dst) + 2 * i;
    o[0] = __floats2half2_rn(v.x, v.y);
    o[1] = __floats2half2_rn(v.z, v.w);
}

// ============================================================================
// fp16 HMMA NT GEMM. CTA 128x128, 8 warps (64x32), K-chunk 64, 3-stage cp.async.
// MODE 0 (fused QKV): grid.x covers 3*Cc columns; W/bias/out selected by n0>>10;
//                     fp16 out scattered to [B,H,T,D].
// MODE 1 (out proj):  fp32 out row-major [M,N].
// ============================================================================
#define GSTAGE 32768
#define GSMEM  (3 * GSTAGE)

__device__ __forceinline__ void gemm_issue(uint32_t sA, uint32_t sB,
                                           const __half* __restrict__ A,
                                           const __half* __restrict__ B,
                                           int m0, int n0, int k0, int tid)
{
#pragma unroll
    for (int it = 0; it < 4; it++) {
        int e = tid + (it << 8);
        int row = e >> 3, cb = e & 7;
        uint32_t off = (uint32_t)(row * 128 + ((cb ^ (row & 7)) << 4));
        cpasync16(sA + off, A + (size_t)(m0 + row) * Cc + k0 + (cb << 3));
        cpasync16(sB + off, B + (size_t)(n0 + row) * Cc + k0 + (cb << 3));
    }
}

template <int MODE>
__global__ void __launch_bounds__(256, 2)
gemm_h(const __half* __restrict__ A,
       const __half* __restrict__ B0, const __half* __restrict__ B1,
       const __half* __restrict__ B2,
       const float* __restrict__ bias0, const float* __restrict__ bias1,
       const float* __restrict__ bias2,
       void* __restrict__ C0, void* __restrict__ C1, void* __restrict__ C2)
{
    extern __shared__ __align__(16) char gsm[];
    const uint32_t sb = smem_u32(gsm);

    const int tid  = threadIdx.x;
    const int lane = tid & 31;
    const int wid  = tid >> 5;
    const int wm   = (wid >> 2) << 6;
    const int wn   = (wid & 3) << 5;
    const int m0   = blockIdx.y << 7;
    const int gn0  = blockIdx.x << 7;

    const int sel = gn0 >> 10;                       // 0 for MODE 1 (grid.x=8)
    const int n0  = gn0 & 1023;
    const __half* B = (sel == 0) ? B0 : (sel == 1) ? B1 : B2;
    const float* bias = (sel == 0) ? bias0 : (sel == 1) ? bias1 : bias2;
    void* Cout = (sel == 0) ? C0 : (sel == 1) ? C1 : C2;

    const int rowa_l = (lane & 7) + (((lane >> 3) & 1) << 3);
    const int cba_l  = lane >> 4;
    const int rowb_l = (lane & 7) + ((lane >> 4) << 3);
    const int cbb_l  = (lane >> 3) & 1;

    float c[4][4][4];
#pragma unroll
    for (int i = 0; i < 4; i++)
#pragma unroll
        for (int j = 0; j < 4; j++)
#pragma unroll
            for (int q = 0; q < 4; q++) c[i][j][q] = 0.f;

    const int nch = Cc / 64;

    gemm_issue(sb, sb + 16384, A, B, m0, n0, 0, tid);
    CPCOMMIT();
    gemm_issue(sb + GSTAGE, sb + GSTAGE + 16384, A, B, m0, n0, 64, tid);
    CPCOMMIT();

    for (int ch = 0; ch < nch; ch++) {
        if (ch + 1 < nch) { CPWAIT(1); } else { CPWAIT(0); }
        __syncthreads();
        if (ch + 2 < nch) {
            uint32_t st = sb + (uint32_t)((ch + 2) % 3) * GSTAGE;
            gemm_issue(st, st + 16384, A, B, m0, n0, (ch + 2) << 6, tid);
            CPCOMMIT();
        }

        const uint32_t sA = sb + (uint32_t)(ch % 3) * GSTAGE;
        const uint32_t sB = sA + 16384;

#pragma unroll
        for (int ks = 0; ks < 4; ks++) {
            uint32_t bf[8];
#pragma unroll
            for (int ntp = 0; ntp < 2; ntp++) {
                int rowb = wn + (ntp << 4) + rowb_l;
                int cbb = (ks << 1) + cbb_l;
                ldsm_x4(sB + (rowb << 7) + ((cbb ^ (rowb & 7)) << 4),
                        bf[4 * ntp], bf[4 * ntp + 1], bf[4 * ntp + 2], bf[4 * ntp + 3]);
            }
#pragma unroll
            for (int mt = 0; mt < 4; mt++) {
                int rowa = wm + (mt << 4) + rowa_l;
                int cba = (ks << 1) + cba_l;
                uint32_t af[4];
                ldsm_x4(sA + (rowa << 7) + ((cba ^ (rowa & 7)) << 4),
                        af[0], af[1], af[2], af[3]);
#pragma unroll
                for (int ntp = 0; ntp < 2; ntp++) {
                    mma_f16(c[mt][2 * ntp],     af, bf[4 * ntp],     bf[4 * ntp + 1]);
                    mma_f16(c[mt][2 * ntp + 1], af, bf[4 * ntp + 2], bf[4 * ntp + 3]);
                }
            }
        }
        __syncthreads();
    }

#pragma unroll
    for (int mt = 0; mt < 4; mt++) {
#pragma unroll
        for (int n8 = 0; n8 < 4; n8++) {
            int m = m0 + wm + (mt << 4) + (lane >> 2);
            int n = n0 + wn + (n8 << 3) + ((lane & 3) << 1);
            float b0 = bias[n], b1 = bias[n + 1];
            float v00 = c[mt][n8][0] + b0, v01 = c[mt][n8][1] + b1;
            float v10 = c[mt][n8][2] + b0, v11 = c[mt][n8][3] + b1;
            if (MODE == 0) {
                __half* Ch = (__half*)Cout;
                int hh = n >> 6, dd = n & 63;
                int bb = m >> 11, tt = m & 2047;
                size_t d0 = ((size_t)((bb * Hc + hh) * Tc + tt) << 6) + dd;
                int m2 = m + 8;
                int bb2 = m2 >> 11, tt2 = m2 & 2047;
                size_t d1 = ((size_t)((bb2 * Hc + hh) * Tc + tt2) << 6) + dd;
                *(__half2*)&Ch[d0] = __floats2half2_rn(v00, v01);
                *(__half2*)&Ch[d1] = __floats2half2_rn(v10, v11);
            } else {
                float* Cf = (float*)Cout;
                *(float2*)&Cf[(size_t)m * Cc + n]       = make_float2(v00, v01);
                *(float2*)&Cf[(size_t)(m + 8) * Cc + n] = make_float2(v10, v11);
            }
        }
    }
}

// ============================================================================
// Flash attention via fp16 mma.sync, fp32 accum, causal.
// CTA: 128 q x 64 kv, 8 warps x 16 q. K/V tiles double-buffered via cp.async.
// ============================================================================
__global__ void __launch_bounds__(256, 2)
flash_attn(const __half* __restrict__ Q, const __half* __restrict__ K,
           const __half* __restrict__ V, __half* __restrict__ Y)
{
    __shared__ __align__(16) __half Qs[128 * 64];
    __shared__ __align__(16) __half Ks[2][64 * 64];
    __shared__ __align__(16) __half Vs[2][64 * 64];

    const int bh   = blockIdx.y;
    const int b    = bh >> 4;
    const int h    = bh & 15;
    const int qt   = gridDim.x - 1 - blockIdx.x;
    const int m0   = qt << 7;
    const int tid  = threadIdx.x;
    const int lane = tid & 31;
    const int wq   = tid >> 5;
    const int mw   = m0 + (wq << 4);
    const size_t base = (size_t)bh * Tc * Dc;
    const float cS = 0.125f * 1.4426950408889634f;

    const uint32_t qsb = smem_u32(Qs);
    const uint32_t ksb = smem_u32(Ks[0]);
    const uint32_t vsb = smem_u32(Vs[0]);

    // Q tile
#pragma unroll
    for (int it = 0; it < 4; it++) {
        int e = tid + (it << 8);
        int row = e >> 3, cb = e & 7;
        *(uint4*)&Qs[(row << 6) + ((cb ^ (row & 7)) << 3)] =
            *(const uint4*)&Q[base + (size_t)(m0 + row) * Dc + (cb << 3)];
    }

    // issue K/V tile 0 into buffer 0 (overlaps with Q ldmatrix below)
    {
        int e = tid << 1;                     // two 16B blocks per thread
#pragma unroll
        for (int u = 0; u < 2; u++) {
            int ee = e + u;
            int row = ee >> 3, cb = ee & 7;
            uint32_t off = (uint32_t)((row << 7) + ((cb ^ (row & 7)) << 4));
            cpasync16(ksb + off, K + base + (size_t)row * Dc + (cb << 3));
            cpasync16(vsb + off, V + base + (size_t)row * Dc + (cb << 3));
        }
        CPCOMMIT();
    }
    __syncthreads();

    uint32_t qf[4][4];
    {
        int rowq = (wq << 4) + (lane & 7) + (((lane >> 3) & 1) << 3);
#pragma unroll
        for (int ks = 0; ks < 4; ks++) {
            int cb = (ks << 1) + (lane >> 4);
            ldsm_x4(qsb + (rowq << 7) + ((cb ^ (rowq & 7)) << 4),
                    qf[ks][0], qf[ks][1], qf[ks][2], qf[ks][3]);
        }
    }

    const int rowk_b = (lane & 7) + ((lane >> 4) << 3);
    const int cbk_b  = (lane >> 3) & 1;
    const int rowv_b = (lane & 7) + (((lane >> 3) & 1) << 3);
    const int cbv_b  = (lane >> 4);

    float oacc[8][4];
#pragma unroll
    for (int i = 0; i < 8; i++)
#pragma unroll
        for (int j = 0; j < 4; j++) oacc[i][j] = 0.f;
    float mrow0 = -1e30f, mrow1 = -1e30f, lrow0 = 0.f, lrow1 = 0.f;

    const int nkv = (qt << 1) + 2;
    for (int j = 0; j < nkv; j++) {
        const int cur = j & 1;
        CPWAIT(0);
        __syncthreads();

        // issue next tile into the other buffer (its readers finished before
        // the sync above, since they ran in iteration j-1)
        if (j + 1 < nkv) {
            const int nb = cur ^ 1;
            const size_t nsrc = base + (size_t)((j + 1) << 6) * Dc;
            int e = tid << 1;
#pragma unroll
            for (int u = 0; u < 2; u++) {
                int ee = e + u;
                int row = ee >> 3, cb = ee & 7;
                uint32_t off = (uint32_t)((row << 7) + ((cb ^ (row & 7)) << 4));
                cpasync16(ksb + (nb << 13) + off, K + nsrc + (size_t)row * Dc + (cb << 3));
                cpasync16(vsb + (nb << 13) + off, V + nsrc + (size_t)row * Dc + (cb << 3));
            }
            CPCOMMIT();
        }

        const int n0 = j << 6;
        if (n0 <= mw + 15) {
            const uint32_t kcb = ksb + (cur << 13);
            const uint32_t vcb = vsb + (cur << 13);

            float sacc[8][4];
#pragma unroll
            for (int i = 0; i < 8; i++)
#pragma unroll
                for (int q = 0; q < 4; q++) sacc[i][q] = 0.f;
#pragma unroll
            for (int ks = 0; ks < 4; ks++) {
#pragma unroll
                for (int ntp = 0; ntp < 4; ntp++) {
                    int rowk = (ntp << 4) + rowk_b;
                    int cbk = (ks << 1) + cbk_b;
                    uint32_t b0, b1, b2, b3;
                    ldsm_x4(kcb + (rowk << 7) + ((cbk ^ (rowk & 7)) << 4), b0, b1, b2, b3);
                    mma_f16(sacc[2 * ntp],     qf[ks], b0, b1);
                    mma_f16(sacc[2 * ntp + 1], qf[ks], b2, b3);
                }
            }
#pragma unroll
            for (int nt = 0; nt < 8; nt++) {
                sacc[nt][0] *= cS; sacc[nt][1] *= cS;
                sacc[nt][2] *= cS; sacc[nt][3] *= cS;
            }

            if (n0 + 63 > mw) {
                int mA = mw + (lane >> 2), mB = mA + 8;
#pragma unroll
                for (int nt = 0; nt < 8; nt++) {
                    int n = n0 + (nt << 3) + ((lane & 3) << 1);
                    if (n     > mA) sacc[nt][0] = -1e30f;
                    if (n + 1 > mA) sacc[nt][1] = -1e30f;
                    if (n     > mB) sacc[nt][2] = -1e30f;
                    if (n + 1 > mB) sacc[nt][3] = -1e30f;
                }
            }

            float mx0 = -1e30f, mx1 = -1e30f;
#pragma unroll
            for (int nt = 0; nt < 8; nt++) {
                mx0 = fmaxf(mx0, fmaxf(sacc[nt][0], sacc[nt][1]));
                mx1 = fmaxf(mx1, fmaxf(sacc[nt][2], sacc[nt][3]));
            }
            mx0 = fmaxf(mx0, __shfl_xor_sync(0xffffffffu, mx0, 1));
            mx0 = fmaxf(mx0, __shfl_xor_sync(0xffffffffu, mx0, 2));
            mx1 = fmaxf(mx1, __shfl_xor_sync(0xffffffffu, mx1, 1));
            mx1 = fmaxf(mx1, __shfl_xor_sync(0xffffffffu, mx1, 2));
            float mn0 = fmaxf(mrow0, mx0), mn1 = fmaxf(mrow1, mx1);
            float a0 = exp2f(mrow0 - mn0), a1 = exp2f(mrow1 - mn1);
            mrow0 = mn0; mrow1 = mn1;
            float s0 = 0.f, s1 = 0.f;
#pragma unroll
            for (int nt = 0; nt < 8; nt++) {
                sacc[nt][0] = exp2f(sacc[nt][0] - mn0);
                sacc[nt][1] = exp2f(sacc[nt][1] - mn0);
                sacc[nt][2] = exp2f(sacc[nt][2] - mn1);
                sacc[nt][3] = exp2f(sacc[nt][3] - mn1);
                s0 += sacc[nt][0] + sacc[nt][1];
                s1 += sacc[nt][2] + sacc[nt][3];
            }
            s0 += __shfl_xor_sync(0xffffffffu, s0, 1);
            s0 += __shfl_xor_sync(0xffffffffu, s0, 2);
            s1 += __shfl_xor_sync(0xffffffffu, s1, 1);
            s1 += __shfl_xor_sync(0xffffffffu, s1, 2);
            lrow0 = lrow0 * a0 + s0;
            lrow1 = lrow1 * a1 + s1;
#pragma unroll
            for (int nt = 0; nt < 8; nt++) {
                oacc[nt][0] *= a0; oacc[nt][1] *= a0;
                oacc[nt][2] *= a1; oacc[nt][3] *= a1;
            }

            uint32_t pp[4][4];
#pragma unroll
            for (int kvs = 0; kvs < 4; kvs++) {
                pp[kvs][0] = pkh2(sacc[2 * kvs][0],     sacc[2 * kvs][1]);
                pp[kvs][1] = pkh2(sacc[2 * kvs][2],     sacc[2 * kvs][3]);
                pp[kvs][2] = pkh2(sacc[2 * kvs + 1][0], sacc[2 * kvs + 1][1]);
                pp[kvs][3] = pkh2(sacc[2 * kvs + 1][2], sacc[2 * kvs + 1][3]);
            }
#pragma unroll
            for (int kvs = 0; kvs < 4; kvs++) {
                int rowv = (kvs << 4) + rowv_b;
#pragma unroll
                for (int ntp = 0; ntp < 4; ntp++) {
                    int cbv = (ntp << 1) + cbv_b;
                    uint32_t b0, b1, b2, b3;
                    ldsm_x4_t(vcb + (rowv << 7) + ((cbv ^ (rowv & 7)) << 4), b0, b1, b2, b3);
                    mma_f16(oacc[2 * ntp],     pp[kvs], b0, b1);
                    mma_f16(oacc[2 * ntp + 1], pp[kvs], b2, b3);
                }
            }
        }
    }

    float inv0 = 1.0f / lrow0, inv1 = 1.0f / lrow1;
    int mA = mw + (lane >> 2);
    size_t r0 = (size_t)(b * Tc + mA) * Cc + (h << 6) + ((lane & 3) << 1);
    size_t r1 = r0 + (size_t)8 * Cc;
#pragma unroll
    for (int nt = 0; nt < 8; nt++) {
        *(__half2*)&Y[r0 + (nt << 3)] = __floats2half2_rn(oacc[nt][0] * inv0, oacc[nt][1] * inv0);
        *(__half2*)&Y[r1 + (nt << 3)] = __floats2half2_rn(oacc[nt][2] * inv1, oacc[nt][3] * inv1);
    }
}

// ============================================================================
extern "C" void kernel_launch(void* const* d_in, const int* in_sizes, int n_in,
                              void* d_out, int out_size)
{
    const float* x  = (const float*)d_in[0];
    const float* Wk = (const float*)d_in[1];
    const float* bk = (const float*)d_in[2];
    const float* Wq = (const float*)d_in[3];
    const float* bq = (const float*)d_in[4];
    const float* Wv = (const float*)d_in[5];
    const float* bv = (const float*)d_in[6];
    const float* Wp = (const float*)d_in[7];
    const float* bp = (const float*)d_in[8];
    float* out = (float*)d_out;

    __half *xh, *wqh, *wkh, *wvh, *wph, *qh, *kh, *vh, *yh;
    cudaGetSymbolAddress((void**)&xh,  g_xh);
    cudaGetSymbolAddress((void**)&wqh, g_wqh);
    cudaGetSymbolAddress((void**)&wkh, g_wkh);
    cudaGetSymbolAddress((void**)&wvh, g_wvh);
    cudaGetSymbolAddress((void**)&wph, g_wph);
    cudaGetSymbolAddress((void**)&qh,  g_qh);
    cudaGetSymbolAddress((void**)&kh,  g_kh);
    cudaGetSymbolAddress((void**)&vh,  g_vh);
    cudaGetSymbolAddress((void**)&yh,  g_yh);

    cudaFuncSetAttribute(gemm_h<0>, cudaFuncAttributeMaxDynamicSharedMemorySize, GSMEM);
    cudaFuncSetAttribute(gemm_h<1>, cudaFuncAttributeMaxDynamicSharedMemorySize, GSMEM);

    // fp32 -> fp16 staging
    const int nx4 = (Mtot * Cc) / 4, nw4 = (Cc * Cc) / 4;
    cvt_h<<<(nx4 + 255) / 256, 256>>>(x, xh, nx4);
    dim3 wg((nw4 + 255) / 256, 4);
    cvt_w4<<<wg, 256>>>(Wq, Wk, Wv, Wp, wqh, wkh, wvh, wph);

    // fused QKV projections: grid.x covers 3*1024 columns
    dim3 gq((3 * Cc) / 128, Mtot / 128);   // (24, 32)
    gemm_h<0><<<gq, 256, GSMEM>>>(xh, wqh, wkh, wvh, bq, bk, bv, qh, kh, vh);

    dim3 fg(Tc / 128, Bc * Hc);            // (16, 32)
    flash_attn<<<fg, 256>>>(qh, kh, vh, yh);

    dim3 gp(Cc / 128, Mtot / 128);         // (8, 32)
    gemm_h<1><<<gp, 256, GSMEM>>>(yh, wph, wph, wph, bp, bp, bp, out, out, out);
}

// round 12
// speedup vs baseline: 8.5204x; 1.0471x over previous
#include <cuda_runtime.h>
#include <cuda_fp16.h>
#include <cstdint>

#define Bc 2
#define Tc 2048
#define Cc 1024
#define Hc 16
#define Dc 64
#define Mtot (Bc * Tc)

// fp16 staging buffers
__device__ __half g_xh[Mtot * Cc];
__device__ __half g_wqh[Cc * Cc];
__device__ __half g_wkh[Cc * Cc];
__device__ __half g_wvh[Cc * Cc];
__device__ __half g_wph[Cc * Cc];
__device__ __half g_qh[Bc * Hc * Tc * Dc];
__device__ __half g_kh[Bc * Hc * Tc * Dc];
__device__ __half g_vh[Bc * Hc * Tc * Dc];
__device__ __half g_yh[Mtot * Cc];

// ============================ PTX helpers ============================
__device__ __forceinline__ uint32_t smem_u32(const void* p) {
    uint32_t a;
    asm("{ .reg .u64 t; cvta.to.shared.u64 t, %1; cvt.u32.u64 %0, t; }" : "=r"(a) : "l"(p));
    return a;
}
__device__ __forceinline__ void ldsm_x4(uint32_t addr, uint32_t& d0, uint32_t& d1,
                                        uint32_t& d2, uint32_t& d3) {
    asm volatile("ldmatrix.sync.aligned.m8n8.x4.shared.b16 {%0,%1,%2,%3}, [%4];"
                 : "=r"(d0), "=r"(d1), "=r"(d2), "=r"(d3) : "r"(addr));
}
__device__ __forceinline__ void ldsm_x4_t(uint32_t addr, uint32_t& d0, uint32_t& d1,
                                          uint32_t& d2, uint32_t& d3) {
    asm volatile("ldmatrix.sync.aligned.m8n8.x4.trans.shared.b16 {%0,%1,%2,%3}, [%4];"
                 : "=r"(d0), "=r"(d1), "=r"(d2), "=r"(d3) : "r"(addr));
}
__device__ __forceinline__ void mma_f16(float* c, const uint32_t* a, uint32_t b0, uint32_t b1) {
    asm volatile("mma.sync.aligned.m16n8k16.row.col.f32.f16.f16.f32 "
                 "{%0,%1,%2,%3}, {%4,%5,%6,%7}, {%8,%9}, {%0,%1,%2,%3};"
                 : "+f"(c[0]), "+f"(c[1]), "+f"(c[2]), "+f"(c[3])
                 : "r"(a[0]), "r"(a[1]), "r"(a[2]), "r"(a[3]), "r"(b0), "r"(b1));
}
__device__ __forceinline__ uint32_t pkh2(float x, float y) {
    __half2 h = __floats2half2_rn(x, y);
    return *reinterpret_cast<uint32_t*>(&h);
}
__device__ __forceinline__ void cpasync16(uint32_t dst, const void* src) {
    asm volatile("cp.async.cg.shared.global [%0], [%1], 16;" :: "r"(dst), "l"(src));
}
#define CPCOMMIT() asm volatile("cp.async.commit_group;" ::: "memory")
#define CPWAIT(n)  asm volatile("cp.async.wait_group %0;" :: "n"(n) : "memory")

// ============================================================================
// fused fp32 -> fp16 convert: x then Wq,Wk,Wv,Wp in one grid
// ============================================================================
#define NX4 (Mtot * Cc / 4)
#define NW4 (Cc * Cc / 4)

__global__ void cvt_all(const float* __restrict__ x,
                        const float* __restrict__ wq, const float* __restrict__ wk,
                        const float* __restrict__ wv, const float* __restrict__ wp,
                        __half* __restrict__ xh,
                        __half* __restrict__ wqh, __half* __restrict__ wkh,
                        __half* __restrict__ wvh, __half* __restrict__ wph)
{
    int i = blockIdx.x * blockDim.x + threadIdx.x;
    const float* src;
    __half* dst;
    int off;
    if (i < NX4) {
        src = x; dst = xh; off = i;
    } else {
        int t = i - NX4;
        int w = t / NW4;
        off = t - w * NW4;
        src = (w == 0) ? wq : (w == 1) ? wk : (w == 2) ? wv : wp;
        dst = (w == 0) ? wqh : (w == 1) ? wkh : (w == 2) ? wvh : wph;
    }
    float4 v = reinterpret_cast<const float4*>(src)[off];
    __half2* o = reinterpret_cast<__half2*>(dst) + 2 * off;
    o[0] = __floats2half2_rn(v.x, v.y);
    o[1] = __floats2half2_rn(v.z, v.w);
}

// ============================================================================
// fp16 HMMA NT GEMM. CTA 128x128, 8 warps (64x32), K-chunk 64, 3-stage cp.async.
// MODE 0 (fused QKV): sel by n0>>10; q output (sel 0) pre-scaled by cS.
// MODE 1 (out proj): fp32 out row-major.
// ============================================================================
#define GSTAGE 32768
#define GSMEM  (3 * GSTAGE)
#define CSCALE 0.18033688f   // 0.125 * log2(e)

__device__ __forceinline__ void gemm_issue(uint32_t sA, uint32_t sB,
                                           const __half* __restrict__ A,
                                           const __half* __restrict__ B,
                                           int m0, int n0, int k0, int tid)
{
#pragma unroll
    for (int it = 0; it < 4; it++) {
        int e = tid + (it << 8);
        int row = e >> 3, cb = e & 7;
        uint32_t off = (uint32_t)(row * 128 + ((cb ^ (row & 7)) << 4));
        cpasync16(sA + off, A + (size_t)(m0 + row) * Cc + k0 + (cb << 3));
        cpasync16(sB + off, B + (size_t)(n0 + row) * Cc + k0 + (cb << 3));
    }
}

template <int MODE>
__global__ void __launch_bounds__(256, 2)
gemm_h(const __half* __restrict__ A,
       const __half* __restrict__ B0, const __half* __restrict__ B1,
       const __half* __restrict__ B2,
       const float* __restrict__ bias0, const float* __restrict__ bias1,
       const float* __restrict__ bias2,
       void* __restrict__ C0, void* __restrict__ C1, void* __restrict__ C2)
{
    extern __shared__ __align__(16) char gsm[];
    const uint32_t sb = smem_u32(gsm);

    const int tid  = threadIdx.x;
    const int lane = tid & 31;
    const int wid  = tid >> 5;
    const int wm   = (wid >> 2) << 6;
    const int wn   = (wid & 3) << 5;
    const int m0   = blockIdx.y << 7;
    const int gn0  = blockIdx.x << 7;

    const int sel = gn0 >> 10;
    const int n0  = gn0 & 1023;
    const __half* B = (sel == 0) ? B0 : (sel == 1) ? B1 : B2;
    const float* bias = (sel == 0) ? bias0 : (sel == 1) ? bias1 : bias2;
    void* Cout = (sel == 0) ? C0 : (sel == 1) ? C1 : C2;
    const float oscale = (MODE == 0 && sel == 0) ? CSCALE : 1.0f;

    const int rowa_l = (lane & 7) + (((lane >> 3) & 1) << 3);
    const int cba_l  = lane >> 4;
    const int rowb_l = (lane & 7) + ((lane >> 4) << 3);
    const int cbb_l  = (lane >> 3) & 1;

    float c[4][4][4];
#pragma unroll
    for (int i = 0; i < 4; i++)
#pragma unroll
        for (int j = 0; j < 4; j++)
#pragma unroll
            for (int q = 0; q < 4; q++) c[i][j][q] = 0.f;

    const int nch = Cc / 64;

    gemm_issue(sb, sb + 16384, A, B, m0, n0, 0, tid);
    CPCOMMIT();
    gemm_issue(sb + GSTAGE, sb + GSTAGE + 16384, A, B, m0, n0, 64, tid);
    CPCOMMIT();

    for (int ch = 0; ch < nch; ch++) {
        if (ch + 1 < nch) { CPWAIT(1); } else { CPWAIT(0); }
        __syncthreads();
        if (ch + 2 < nch) {
            uint32_t st = sb + (uint32_t)((ch + 2) % 3) * GSTAGE;
            gemm_issue(st, st + 16384, A, B, m0, n0, (ch + 2) << 6, tid);
            CPCOMMIT();
        }

        const uint32_t sA = sb + (uint32_t)(ch % 3) * GSTAGE;
        const uint32_t sB = sA + 16384;

#pragma unroll
        for (int ks = 0; ks < 4; ks++) {
            uint32_t bf[8];
#pragma unroll
            for (int ntp = 0; ntp < 2; ntp++) {
                int rowb = wn + (ntp << 4) + rowb_l;
                int cbb = (ks << 1) + cbb_l;
                ldsm_x4(sB + (rowb << 7) + ((cbb ^ (rowb & 7)) << 4),
                        bf[4 * ntp], bf[4 * ntp + 1], bf[4 * ntp + 2], bf[4 * ntp + 3]);
            }
#pragma unroll
            for (int mt = 0; mt < 4; mt++) {
                int rowa = wm + (mt << 4) + rowa_l;
                int cba = (ks << 1) + cba_l;
                uint32_t af[4];
                ldsm_x4(sA + (rowa << 7) + ((cba ^ (rowa & 7)) << 4),
                        af[0], af[1], af[2], af[3]);
#pragma unroll
                for (int ntp = 0; ntp < 2; ntp++) {
                    mma_f16(c[mt][2 * ntp],     af, bf[4 * ntp],     bf[4 * ntp + 1]);
                    mma_f16(c[mt][2 * ntp + 1], af, bf[4 * ntp + 2], bf[4 * ntp + 3]);
                }
            }
        }
        __syncthreads();
    }

#pragma unroll
    for (int mt = 0; mt < 4; mt++) {
#pragma unroll
        for (int n8 = 0; n8 < 4; n8++) {
            int m = m0 + wm + (mt << 4) + (lane >> 2);
            int n = n0 + wn + (n8 << 3) + ((lane & 3) << 1);
            float b0 = bias[n], b1 = bias[n + 1];
            float v00 = (c[mt][n8][0] + b0) * oscale, v01 = (c[mt][n8][1] + b1) * oscale;
            float v10 = (c[mt][n8][2] + b0) * oscale, v11 = (c[mt][n8][3] + b1) * oscale;
            if (MODE == 0) {
                __half* Ch = (__half*)Cout;
                int hh = n >> 6, dd = n & 63;
                int bb = m >> 11, tt = m & 2047;
                size_t d0 = ((size_t)((bb * Hc + hh) * Tc + tt) << 6) + dd;
                int m2 = m + 8;
                int bb2 = m2 >> 11, tt2 = m2 & 2047;
                size_t d1 = ((size_t)((bb2 * Hc + hh) * Tc + tt2) << 6) + dd;
                *(__half2*)&Ch[d0] = __floats2half2_rn(v00, v01);
                *(__half2*)&Ch[d1] = __floats2half2_rn(v10, v11);
            } else {
                float* Cf = (float*)Cout;
                *(float2*)&Cf[(size_t)m * Cc + n]       = make_float2(v00, v01);
                *(float2*)&Cf[(size_t)(m + 8) * Cc + n] = make_float2(v10, v11);
            }
        }
    }
}

// ============================================================================
// Flash attention, fp16 HMMA, fp32 accum, causal. Delayed-PV pipeline:
// at tile j issue S_j MMAs then PV_{j-1} MMAs, softmax_j overlaps with the
// tensor pipe. V triple-buffered (PV needs V_{j-1} alive across prefetch).
// Q pre-scaled by cS in the projection GEMM. Dynamic smem 56KB.
// ============================================================================
#define FSMEM (16384 + 2 * 8192 + 3 * 8192)   // Qs + K[2] + V[3] = 57344

__device__ __forceinline__ void pv_mma(float oacc[8][4], const uint32_t pp[4][4],
                                       uint32_t vcb, int rowv_b, int cbv_b)
{
#pragma unroll
    for (int kvs = 0; kvs < 4; kvs++) {
        int rowv = (kvs << 4) + rowv_b;
#pragma unroll
        for (int ntp = 0; ntp < 4; ntp++) {
            int cbv = (ntp << 1) + cbv_b;
            uint32_t b0, b1, b2, b3;
            ldsm_x4_t(vcb + (rowv << 7) + ((cbv ^ (rowv & 7)) << 4), b0, b1, b2, b3);
            mma_f16(oacc[2 * ntp],     pp[kvs], b0, b1);
            mma_f16(oacc[2 * ntp + 1], pp[kvs], b2, b3);
        }
    }
}

__global__ void __launch_bounds__(256, 2)
flash_attn(const __half* __restrict__ Q, const __half* __restrict__ K,
           const __half* __restrict__ V, __half* __restrict__ Y)
{
    extern __shared__ __align__(16) __half fsm[];
    __half* Qsp = fsm;                       // 8192 halfs
    const uint32_t qsb = smem_u32(fsm);
    const uint32_t ksb = qsb + 16384;        // 2 bufs x 8192B
    const uint32_t vsb = ksb + 16384;        // 3 bufs x 8192B

    const int bh   = blockIdx.y;
    const int b    = bh >> 4;
    const int h    = bh & 15;
    const int qt   = gridDim.x - 1 - blockIdx.x;
    const int m0   = qt << 7;
    const int tid  = threadIdx.x;
    const int lane = tid & 31;
    const int wq   = tid >> 5;
    const int mw   = m0 + (wq << 4);
    const size_t base = (size_t)bh * Tc * Dc;

    // Q tile (already scaled by cS)
#pragma unroll
    for (int it = 0; it < 4; it++) {
        int e = tid + (it << 8);
        int row = e >> 3, cb = e & 7;
        *(uint4*)&Qsp[(row << 6) + ((cb ^ (row & 7)) << 3)] =
            *(const uint4*)&Q[base + (size_t)(m0 + row) * Dc + (cb << 3)];
    }

    // issue K0 -> Kbuf0, V0 -> Vbuf0
    {
        int e = tid << 1;
#pragma unroll
        for (int u = 0; u < 2; u++) {
            int ee = e + u;
            int row = ee >> 3, cb = ee & 7;
            uint32_t off = (uint32_t)((row << 7) + ((cb ^ (row & 7)) << 4));
            cpasync16(ksb + off, K + base + (size_t)row * Dc + (cb << 3));
            cpasync16(vsb + off, V + base + (size_t)row * Dc + (cb << 3));
        }
        CPCOMMIT();
    }
    __syncthreads();

    uint32_t qf[4][4];
    {
        int rowq = (wq << 4) + (lane & 7) + (((lane >> 3) & 1) << 3);
#pragma unroll
        for (int ks = 0; ks < 4; ks++) {
            int cb = (ks << 1) + (lane >> 4);
            ldsm_x4(qsb + (rowq << 7) + ((cb ^ (rowq & 7)) << 4),
                    qf[ks][0], qf[ks][1], qf[ks][2], qf[ks][3]);
        }
    }

    const int rowk_b = (lane & 7) + ((lane >> 4) << 3);
    const int cbk_b  = (lane >> 3) & 1;
    const int rowv_b = (lane & 7) + (((lane >> 3) & 1) << 3);
    const int cbv_b  = (lane >> 4);

    float oacc[8][4];
#pragma unroll
    for (int i = 0; i < 8; i++)
#pragma unroll
        for (int j = 0; j < 4; j++) oacc[i][j] = 0.f;
    float mrow0 = -1e30f, mrow1 = -1e30f, lrow0 = 0.f, lrow1 = 0.f;
    uint32_t pp[4][4];
    bool flushed = false;

    const int nkv = (qt << 1) + 2;
    for (int j = 0; j < nkv; j++) {
        CPWAIT(0);
        __syncthreads();

        if (j + 1 < nkv) {
            const size_t nsrc = base + (size_t)((j + 1) << 6) * Dc;
            const uint32_t kb = ksb + (uint32_t)(((j + 1) & 1) << 13);
            const uint32_t vb = vsb + (uint32_t)(((j + 1) % 3) << 13);
            int e = tid << 1;
#pragma unroll
            for (int u = 0; u < 2; u++) {
                int ee = e + u;
                int row = ee >> 3, cb = ee & 7;
                uint32_t off = (uint32_t)((row << 7) + ((cb ^ (row & 7)) << 4));
                cpasync16(kb + off, K + nsrc + (size_t)row * Dc + (cb << 3));
                cpasync16(vb + off, V + nsrc + (size_t)row * Dc + (cb << 3));
            }
            CPCOMMIT();
        }

        const int n0 = j << 6;
        if (n0 <= mw + 15) {
            const uint32_t kcb = ksb + (uint32_t)((j & 1) << 13);

            // ---- S = Q @ K^T (issue first; softmax below overlaps PV) ----
            float sacc[8][4];
#pragma unroll
            for (int i = 0; i < 8; i++)
#pragma unroll
                for (int q = 0; q < 4; q++) sacc[i][q] = 0.f;
#pragma unroll
            for (int ks = 0; ks < 4; ks++) {
#pragma unroll
                for (int ntp = 0; ntp < 4; ntp++) {
                    int rowk = (ntp << 4) + rowk_b;
                    int cbk = (ks << 1) + cbk_b;
                    uint32_t b0, b1, b2, b3;
                    ldsm_x4(kcb + (rowk << 7) + ((cbk ^ (rowk & 7)) << 4), b0, b1, b2, b3);
                    mma_f16(sacc[2 * ntp],     qf[ks], b0, b1);
                    mma_f16(sacc[2 * ntp + 1], qf[ks], b2, b3);
                }
            }

            // ---- deferred PV of tile j-1 (independent of sacc) ----
            if (j > 0)
                pv_mma(oacc, pp, vsb + (uint32_t)(((j - 1) % 3) << 13), rowv_b, cbv_b);

            // ---- causal mask ----
            if (n0 + 63 > mw) {
                int mA = mw + (lane >> 2), mB = mA + 8;
#pragma unroll
                for (int nt = 0; nt < 8; nt++) {
                    int n = n0 + (nt << 3) + ((lane & 3) << 1);
                    if (n     > mA) sacc[nt][0] = -1e30f;
                    if (n + 1 > mA) sacc[nt][1] = -1e30f;
                    if (n     > mB) sacc[nt][2] = -1e30f;
                    if (n + 1 > mB) sacc[nt][3] = -1e30f;
                }
            }

            // ---- online softmax (scores already in log2 units) ----
            float mx0 = -1e30f, mx1 = -1e30f;
#pragma unroll
            for (int nt = 0; nt < 8; nt++) {
                mx0 = fmaxf(mx0, fmaxf(sacc[nt][0], sacc[nt][1]));
                mx1 = fmaxf(mx1, fmaxf(sacc[nt][2], sacc[nt][3]));
            }
            mx0 = fmaxf(mx0, __shfl_xor_sync(0xffffffffu, mx0, 1));
            mx0 = fmaxf(mx0, __shfl_xor_sync(0xffffffffu, mx0, 2));
            mx1 = fmaxf(mx1, __shfl_xor_sync(0xffffffffu, mx1, 1));
            mx1 = fmaxf(mx1, __shfl_xor_sync(0xffffffffu, mx1, 2));
            float mn0 = fmaxf(mrow0, mx0), mn1 = fmaxf(mrow1, mx1);
            float a0 = exp2f(mrow0 - mn0), a1 = exp2f(mrow1 - mn1);
            mrow0 = mn0; mrow1 = mn1;
            float s0 = 0.f, s1 = 0.f;
#pragma unroll
            for (int nt = 0; nt < 8; nt++) {
                sacc[nt][0] = exp2f(sacc[nt][0] - mn0);
                sacc[nt][1] = exp2f(sacc[nt][1] - mn0);
                sacc[nt][2] = exp2f(sacc[nt][2] - mn1);
                sacc[nt][3] = exp2f(sacc[nt][3] - mn1);
                s0 += sacc[nt][0] + sacc[nt][1];
                s1 += sacc[nt][2] + sacc[nt][3];
            }
            s0 += __shfl_xor_sync(0xffffffffu, s0, 1);
            s0 += __shfl_xor_sync(0xffffffffu, s0, 2);
            s1 += __shfl_xor_sync(0xffffffffu, s1, 1);
            s1 += __shfl_xor_sync(0xffffffffu, s1, 2);
            lrow0 = lrow0 * a0 + s0;
            lrow1 = lrow1 * a1 + s1;

            // rescale AFTER PV_{j-1} was added (telescoping alpha product)
#pragma unroll
            for (int nt = 0; nt < 8; nt++) {
                oacc[nt][0] *= a0; oacc[nt][1] *= a0;
                oacc[nt][2] *= a1; oacc[nt][3] *= a1;
            }

            // pack P_j for next iteration's PV
#pragma unroll
            for (int kvs = 0; kvs < 4; kvs++) {
                pp[kvs][0] = pkh2(sacc[2 * kvs][0],     sacc[2 * kvs][1]);
                pp[kvs][1] = pkh2(sacc[2 * kvs][2],     sacc[2 * kvs][3]);
                pp[kvs][2] = pkh2(sacc[2 * kvs + 1][0], sacc[2 * kvs + 1][1]);
                pp[kvs][3] = pkh2(sacc[2 * kvs + 1][2], sacc[2 * kvs + 1][3]);
            }
        } else if (!flushed) {
            // first skipped tile: flush pending PV (V_{j-1} still live, mod-3)
            pv_mma(oacc, pp, vsb + (uint32_t)(((j - 1) % 3) << 13), rowv_b, cbv_b);
            flushed = true;
        }
    }
    if (!flushed)
        pv_mma(oacc, pp, vsb + (uint32_t)(((nkv - 1) % 3) << 13), rowv_b, cbv_b);

    float inv0 = 1.0f / lrow0, inv1 = 1.0f / lrow1;
    int mA = mw + (lane >> 2);
    size_t r0 = (size_t)(b * Tc + mA) * Cc + (h << 6) + ((lane & 3) << 1);
    size_t r1 = r0 + (size_t)8 * Cc;
#pragma unroll
    for (int nt = 0; nt < 8; nt++) {
        *(__half2*)&Y[r0 + (nt << 3)] = __floats2half2_rn(oacc[nt][0] * inv0, oacc[nt][1] * inv0);
        *(__half2*)&Y[r1 + (nt << 3)] = __floats2half2_rn(oacc[nt][2] * inv1, oacc[nt][3] * inv1);
    }
}

// ============================================================================
extern "C" void kernel_launch(void* const* d_in, const int* in_sizes, int n_in,
                              void* d_out, int out_size)
{
    const float* x  = (const float*)d_in[0];
    const float* Wk = (const float*)d_in[1];
    const float* bk = (const float*)d_in[2];
    const float* Wq = (const float*)d_in[3];
    const float* bq = (const float*)d_in[4];
    const float* Wv = (const float*)d_in[5];
    const float* bv = (const float*)d_in[6];
    const float* Wp = (const float*)d_in[7];
    const float* bp = (const float*)d_in[8];
    float* out = (float*)d_out;

    __half *xh, *wqh, *wkh, *wvh, *wph, *qh, *kh, *vh, *yh;
    cudaGetSymbolAddress((void**)&xh,  g_xh);
    cudaGetSymbolAddress((void**)&wqh, g_wqh);
    cudaGetSymbolAddress((void**)&wkh, g_wkh);
    cudaGetSymbolAddress((void**)&wvh, g_wvh);
    cudaGetSymbolAddress((void**)&wph, g_wph);
    cudaGetSymbolAddress((void**)&qh,  g_qh);
    cudaGetSymbolAddress((void**)&kh,  g_kh);
    cudaGetSymbolAddress((void**)&vh,  g_vh);
    cudaGetSymbolAddress((void**)&yh,  g_yh);

    cudaFuncSetAttribute(gemm_h<0>, cudaFuncAttributeMaxDynamicSharedMemorySize, GSMEM);
    cudaFuncSetAttribute(gemm_h<1>, cudaFuncAttributeMaxDynamicSharedMemorySize, GSMEM);
    cudaFuncSetAttribute(flash_attn, cudaFuncAttributeMaxDynamicSharedMemorySize, FSMEM);

    // fused fp32 -> fp16 staging (x + 4 weights, one launch)
    const int ntot = NX4 + 4 * NW4;
    cvt_all<<<(ntot + 255) / 256, 256>>>(x, Wq, Wk, Wv, Wp, xh, wqh, wkh, wvh, wph);

    // fused QKV projections (q pre-scaled by cS in epilogue)
    dim3 gq((3 * Cc) / 128, Mtot / 128);   // (24, 32)
    gemm_h<0><<<gq, 256, GSMEM>>>(xh, wqh, wkh, wvh, bq, bk, bv, qh, kh, vh);

    dim3 fg(Tc / 128, Bc * Hc);            // (16, 32)
    flash_attn<<<fg, 256, FSMEM>>>(qh, kh, vh, yh);

    dim3 gp(Cc / 128, Mtot / 128);         // (8, 32)
    gemm_h<1><<<gp, 256, GSMEM>>>(yh, wph, wph, wph, bp, bp, bp, out, out, out);
}

// round 13
// speedup vs baseline: 8.8136x; 1.0344x over previous
#include <cuda_runtime.h>
#include <cuda_fp16.h>
#include <cstdint>

#define Bc 2
#define Tc 2048
#define Cc 1024
#define Hc 16
#define Dc 64
#define Mtot (Bc * Tc)

// fp16 staging buffers
__device__ __half g_xh[Mtot * Cc];
__device__ __half g_wqh[Cc * Cc];
__device__ __half g_wkh[Cc * Cc];
__device__ __half g_wvh[Cc * Cc];
__device__ __half g_wph[Cc * Cc];
__device__ __half g_qh[Bc * Hc * Tc * Dc];
__device__ __half g_kh[Bc * Hc * Tc * Dc];
__device__ __half g_vh[Bc * Hc * Tc * Dc];
__device__ __half g_yh[Mtot * Cc];

// ============================ PTX helpers ============================
__device__ __forceinline__ uint32_t smem_u32(const void* p) {
    uint32_t a;
    asm("{ .reg .u64 t; cvta.to.shared.u64 t, %1; cvt.u32.u64 %0, t; }" : "=r"(a) : "l"(p));
    return a;
}
__device__ __forceinline__ void ldsm_x4(uint32_t addr, uint32_t& d0, uint32_t& d1,
                                        uint32_t& d2, uint32_t& d3) {
    asm volatile("ldmatrix.sync.aligned.m8n8.x4.shared.b16 {%0,%1,%2,%3}, [%4];"
                 : "=r"(d0), "=r"(d1), "=r"(d2), "=r"(d3) : "r"(addr));
}
__device__ __forceinline__ void ldsm_x4_t(uint32_t addr, uint32_t& d0, uint32_t& d1,
                                          uint32_t& d2, uint32_t& d3) {
    asm volatile("ldmatrix.sync.aligned.m8n8.x4.trans.shared.b16 {%0,%1,%2,%3}, [%4];"
                 : "=r"(d0), "=r"(d1), "=r"(d2), "=r"(d3) : "r"(addr));
}
__device__ __forceinline__ void mma_f16(float* c, const uint32_t* a, uint32_t b0, uint32_t b1) {
    asm volatile("mma.sync.aligned.m16n8k16.row.col.f32.f16.f16.f32 "
                 "{%0,%1,%2,%3}, {%4,%5,%6,%7}, {%8,%9}, {%0,%1,%2,%3};"
                 : "+f"(c[0]), "+f"(c[1]), "+f"(c[2]), "+f"(c[3])
                 : "r"(a[0]), "r"(a[1]), "r"(a[2]), "r"(a[3]), "r"(b0), "r"(b1));
}
__device__ __forceinline__ uint32_t pkh2(float x, float y) {
    __half2 h = __floats2half2_rn(x, y);
    return *reinterpret_cast<uint32_t*>(&h);
}
__device__ __forceinline__ uint32_t ex2h2(uint32_t in) {
    uint32_t r; asm("ex2.approx.f16x2 %0, %1;" : "=r"(r) : "r"(in)); return r;
}
__device__ __forceinline__ void cpasync16(uint32_t dst, const void* src) {
    asm volatile("cp.async.cg.shared.global [%0], [%1], 16;" :: "r"(dst), "l"(src));
}
#define CPCOMMIT() asm volatile("cp.async.commit_group;" ::: "memory")
#define CPWAIT(n)  asm volatile("cp.async.wait_group %0;" :: "n"(n) : "memory")
#define HONES 0x3C003C00u   // half2(1.0, 1.0)

// ============================================================================
// fused fp32 -> fp16 convert: x then Wq,Wk,Wv,Wp in one grid
// ============================================================================
#define NX4 (Mtot * Cc / 4)
#define NW4 (Cc * Cc / 4)

__global__ void cvt_all(const float* __restrict__ x,
                        const float* __restrict__ wq, const float* __restrict__ wk,
                        const float* __restrict__ wv, const float* __restrict__ wp,
                        __half* __restrict__ xh,
                        __half* __restrict__ wqh, __half* __restrict__ wkh,
                        __half* __restrict__ wvh, __half* __restrict__ wph)
{
    int i = blockIdx.x * blockDim.x + threadIdx.x;
    const float* src;
    __half* dst;
    int off;
    if (i < NX4) {
        src = x; dst = xh; off = i;
    } else {
        int t = i - NX4;
        int w = t / NW4;
        off = t - w * NW4;
        src = (w == 0) ? wq : (w == 1) ? wk : (w == 2) ? wv : wp;
        dst = (w == 0) ? wqh : (w == 1) ? wkh : (w == 2) ? wvh : wph;
    }
    float4 v = reinterpret_cast<const float4*>(src)[off];
    __half2* o = reinterpret_cast<__half2*>(dst) + 2 * off;
    o[0] = __floats2half2_rn(v.x, v.y);
    o[1] = __floats2half2_rn(v.z, v.w);
}

// ============================================================================
// fp16 HMMA NT GEMM. CTA 128x128, 8 warps (64x32), K-chunk 64, 3-stage cp.async.
// Inner loop: batch ALL fragment loads (8 B + 16 A ldsm regs) before the 32
// MMAs so ldmatrix latency overlaps across loads.
// MODE 0 (fused QKV): sel by n0>>10; q output (sel 0) pre-scaled by cS.
// MODE 1 (out proj): fp32 out row-major.
// ============================================================================
#define GSTAGE 32768
#define GSMEM  (3 * GSTAGE)
#define CSCALE 0.18033688f   // 0.125 * log2(e)

__device__ __forceinline__ void gemm_issue(uint32_t sA, uint32_t sB,
                                           const __half* __restrict__ A,
                                           const __half* __restrict__ B,
                                           int m0, int n0, int k0, int tid)
{
#pragma unroll
    for (int it = 0; it < 4; it++) {
        int e = tid + (it << 8);
        int row = e >> 3, cb = e & 7;
        uint32_t off = (uint32_t)(row * 128 + ((cb ^ (row & 7)) << 4));
        cpasync16(sA + off, A + (size_t)(m0 + row) * Cc + k0 + (cb << 3));
        cpasync16(sB + off, B + (size_t)(n0 + row) * Cc + k0 + (cb << 3));
    }
}

template <int MODE>
__global__ void __launch_bounds__(256, 2)
gemm_h(const __half* __restrict__ A,
       const __half* __restrict__ B0, const __half* __restrict__ B1,
       const __half* __restrict__ B2,
       const float* __restrict__ bias0, const float* __restrict__ bias1,
       const float* __restrict__ bias2,
       void* __restrict__ C0, void* __restrict__ C1, void* __restrict__ C2)
{
    extern __shared__ __align__(16) char gsm[];
    const uint32_t sb = smem_u32(gsm);

    const int tid  = threadIdx.x;
    const int lane = tid & 31;
    const int wid  = tid >> 5;
    const int wm   = (wid >> 2) << 6;
    const int wn   = (wid & 3) << 5;
    const int m0   = blockIdx.y << 7;
    const int gn0  = blockIdx.x << 7;

    const int sel = gn0 >> 10;
    const int n0  = gn0 & 1023;
    const __half* B = (sel == 0) ? B0 : (sel == 1) ? B1 : B2;
    const float* bias = (sel == 0) ? bias0 : (sel == 1) ? bias1 : bias2;
    void* Cout = (sel == 0) ? C0 : (sel == 1) ? C1 : C2;
    const float oscale = (MODE == 0 && sel == 0) ? CSCALE : 1.0f;

    const int rowa_l = (lane & 7) + (((lane >> 3) & 1) << 3);
    const int cba_l  = lane >> 4;
    const int rowb_l = (lane & 7) + ((lane >> 4) << 3);
    const int cbb_l  = (lane >> 3) & 1;

    float c[4][4][4];
#pragma unroll
    for (int i = 0; i < 4; i++)
#pragma unroll
        for (int j = 0; j < 4; j++)
#pragma unroll
            for (int q = 0; q < 4; q++) c[i][j][q] = 0.f;

    const int nch = Cc / 64;

    gemm_issue(sb, sb + 16384, A, B, m0, n0, 0, tid);
    CPCOMMIT();
    gemm_issue(sb + GSTAGE, sb + GSTAGE + 16384, A, B, m0, n0, 64, tid);
    CPCOMMIT();

    for (int ch = 0; ch < nch; ch++) {
        if (ch + 1 < nch) { CPWAIT(1); } else { CPWAIT(0); }
        __syncthreads();
        if (ch + 2 < nch) {
            uint32_t st = sb + (uint32_t)((ch + 2) % 3) * GSTAGE;
            gemm_issue(st, st + 16384, A, B, m0, n0, (ch + 2) << 6, tid);
            CPCOMMIT();
        }

        const uint32_t sA = sb + (uint32_t)(ch % 3) * GSTAGE;
        const uint32_t sB = sA + 16384;

#pragma unroll
        for (int ks = 0; ks < 4; ks++) {
            // batch: 2 B-ldsm + 4 A-ldsm issued back-to-back, then 32 MMAs
            uint32_t bf[8];
#pragma unroll
            for (int ntp = 0; ntp < 2; ntp++) {
                int rowb = wn + (ntp << 4) + rowb_l;
                int cbb = (ks << 1) + cbb_l;
                ldsm_x4(sB + (rowb << 7) + ((cbb ^ (rowb & 7)) << 4),
                        bf[4 * ntp], bf[4 * ntp + 1], bf[4 * ntp + 2], bf[4 * ntp + 3]);
            }
            uint32_t af[4][4];
#pragma unroll
            for (int mt = 0; mt < 4; mt++) {
                int rowa = wm + (mt << 4) + rowa_l;
                int cba = (ks << 1) + cba_l;
                ldsm_x4(sA + (rowa << 7) + ((cba ^ (rowa & 7)) << 4),
                        af[mt][0], af[mt][1], af[mt][2], af[mt][3]);
            }
#pragma unroll
            for (int mt = 0; mt < 4; mt++)
#pragma unroll
                for (int ntp = 0; ntp < 2; ntp++) {
                    mma_f16(c[mt][2 * ntp],     af[mt], bf[4 * ntp],     bf[4 * ntp + 1]);
                    mma_f16(c[mt][2 * ntp + 1], af[mt], bf[4 * ntp + 2], bf[4 * ntp + 3]);
                }
        }
        __syncthreads();
    }

#pragma unroll
    for (int mt = 0; mt < 4; mt++) {
#pragma unroll
        for (int n8 = 0; n8 < 4; n8++) {
            int m = m0 + wm + (mt << 4) + (lane >> 2);
            int n = n0 + wn + (n8 << 3) + ((lane & 3) << 1);
            float b0 = bias[n], b1 = bias[n + 1];
            float v00 = (c[mt][n8][0] + b0) * oscale, v01 = (c[mt][n8][1] + b1) * oscale;
            float v10 = (c[mt][n8][2] + b0) * oscale, v11 = (c[mt][n8][3] + b1) * oscale;
            if (MODE == 0) {
                __half* Ch = (__half*)Cout;
                int hh = n >> 6, dd = n & 63;
                int bb = m >> 11, tt = m & 2047;
                size_t d0 = ((size_t)((bb * Hc + hh) * Tc + tt) << 6) + dd;
                int m2 = m + 8;
                int bb2 = m2 >> 11, tt2 = m2 & 2047;
                size_t d1 = ((size_t)((bb2 * Hc + hh) * Tc + tt2) << 6) + dd;
                *(__half2*)&Ch[d0] = __floats2half2_rn(v00, v01);
                *(__half2*)&Ch[d1] = __floats2half2_rn(v10, v11);
            } else {
                float* Cf = (float*)Cout;
                *(float2*)&Cf[(size_t)m * Cc + n]       = make_float2(v00, v01);
                *(float2*)&Cf[(size_t)(m + 8) * Cc + n] = make_float2(v10, v11);
            }
        }
    }
}

// ============================================================================
// Flash attention, fp16 HMMA, fp32 accum, causal. Delayed-PV pipeline +
// f16x2 exponentials + row-sum via ones-MMA (l accumulated in a fragment,
// rescaled with the same alpha as oacc -> exact telescoping, no sum shfl).
// ============================================================================
#define FSMEM (16384 + 2 * 8192 + 3 * 8192)   // Qs + K[2] + V[3] = 57344

__device__ __forceinline__ void pv_mma(float oacc[8][4], const uint32_t pp[4][4],
                                       uint32_t vcb, int rowv_b, int cbv_b)
{
#pragma unroll
    for (int kvs = 0; kvs < 4; kvs++) {
        int rowv = (kvs << 4) + rowv_b;
        uint32_t vf[4][4];
#pragma unroll
        for (int ntp = 0; ntp < 4; ntp++) {
            int cbv = (ntp << 1) + cbv_b;
            ldsm_x4_t(vcb + (rowv << 7) + ((cbv ^ (rowv & 7)) << 4),
                      vf[ntp][0], vf[ntp][1], vf[ntp][2], vf[ntp][3]);
        }
#pragma unroll
        for (int ntp = 0; ntp < 4; ntp++) {
            mma_f16(oacc[2 * ntp],     pp[kvs], vf[ntp][0], vf[ntp][1]);
            mma_f16(oacc[2 * ntp + 1], pp[kvs], vf[ntp][2], vf[ntp][3]);
        }
    }
}

__global__ void __launch_bounds__(256, 2)
flash_attn(const __half* __restrict__ Q, const __half* __restrict__ K,
           const __half* __restrict__ V, __half* __restrict__ Y)
{
    extern __shared__ __align__(16) __half fsm[];
    __half* Qsp = fsm;
    const uint32_t qsb = smem_u32(fsm);
    const uint32_t ksb = qsb + 16384;
    const uint32_t vsb = ksb + 16384;

    const int bh   = blockIdx.y;
    const int b    = bh >> 4;
    const int h    = bh & 15;
    const int qt   = gridDim.x - 1 - blockIdx.x;
    const int m0   = qt << 7;
    const int tid  = threadIdx.x;
    const int lane = tid & 31;
    const int wq   = tid >> 5;
    const int mw   = m0 + (wq << 4);
    const size_t base = (size_t)bh * Tc * Dc;

    // Q tile (pre-scaled by cS in the projection)
#pragma unroll
    for (int it = 0; it < 4; it++) {
        int e = tid + (it << 8);
        int row = e >> 3, cb = e & 7;
        *(uint4*)&Qsp[(row << 6) + ((cb ^ (row & 7)) << 3)] =
            *(const uint4*)&Q[base + (size_t)(m0 + row) * Dc + (cb << 3)];
    }

    // issue K0/V0
    {
        int e = tid << 1;
#pragma unroll
        for (int u = 0; u < 2; u++) {
            int ee = e + u;
            int row = ee >> 3, cb = ee & 7;
            uint32_t off = (uint32_t)((row << 7) + ((cb ^ (row & 7)) << 4));
            cpasync16(ksb + off, K + base + (size_t)row * Dc + (cb << 3));
            cpasync16(vsb + off, V + base + (size_t)row * Dc + (cb << 3));
        }
        CPCOMMIT();
    }
    __syncthreads();

    uint32_t qf[4][4];
    {
        int rowq = (wq << 4) + (lane & 7) + (((lane >> 3) & 1) << 3);
#pragma unroll
        for (int ks = 0; ks < 4; ks++) {
            int cb = (ks << 1) + (lane >> 4);
            ldsm_x4(qsb + (rowq << 7) + ((cb ^ (rowq & 7)) << 4),
                    qf[ks][0], qf[ks][1], qf[ks][2], qf[ks][3]);
        }
    }

    const int rowk_b = (lane & 7) + ((lane >> 4) << 3);
    const int cbk_b  = (lane >> 3) & 1;
    const int rowv_b = (lane & 7) + (((lane >> 3) & 1) << 3);
    const int cbv_b  = (lane >> 4);

    float oacc[8][4];
#pragma unroll
    for (int i = 0; i < 8; i++)
#pragma unroll
        for (int j = 0; j < 4; j++) oacc[i][j] = 0.f;
    float lacc[4] = {0.f, 0.f, 0.f, 0.f};
    float mrow0 = -1e30f, mrow1 = -1e30f;
    uint32_t pp[4][4];
    bool flushed = false;

    const int nkv = (qt << 1) + 2;
    for (int j = 0; j < nkv; j++) {
        CPWAIT(0);
        __syncthreads();

        if (j + 1 < nkv) {
            const size_t nsrc = base + (size_t)((j + 1) << 6) * Dc;
            const uint32_t kb = ksb + (uint32_t)(((j + 1) & 1) << 13);
            const uint32_t vb = vsb + (uint32_t)(((j + 1) % 3) << 13);
            int e = tid << 1;
#pragma unroll
            for (int u = 0; u < 2; u++) {
                int ee = e + u;
                int row = ee >> 3, cb = ee & 7;
                uint32_t off = (uint32_t)((row << 7) + ((cb ^ (row & 7)) << 4));
                cpasync16(kb + off, K + nsrc + (size_t)row * Dc + (cb << 3));
                cpasync16(vb + off, V + nsrc + (size_t)row * Dc + (cb << 3));
            }
            CPCOMMIT();
        }

        const int n0 = j << 6;
        if (n0 <= mw + 15) {
            const uint32_t kcb = ksb + (uint32_t)((j & 1) << 13);

            // ---- S = Q @ K^T (batched ldsm, then MMAs) ----
            float sacc[8][4];
#pragma unroll
            for (int i = 0; i < 8; i++)
#pragma unroll
                for (int q = 0; q < 4; q++) sacc[i][q] = 0.f;
#pragma unroll
            for (int ks = 0; ks < 4; ks++) {
                uint32_t kf[4][4];
#pragma unroll
                for (int ntp = 0; ntp < 4; ntp++) {
                    int rowk = (ntp << 4) + rowk_b;
                    int cbk = (ks << 1) + cbk_b;
                    ldsm_x4(kcb + (rowk << 7) + ((cbk ^ (rowk & 7)) << 4),
                            kf[ntp][0], kf[ntp][1], kf[ntp][2], kf[ntp][3]);
                }
#pragma unroll
                for (int ntp = 0; ntp < 4; ntp++) {
                    mma_f16(sacc[2 * ntp],     qf[ks], kf[ntp][0], kf[ntp][1]);
                    mma_f16(sacc[2 * ntp + 1], qf[ks], kf[ntp][2], kf[ntp][3]);
                }
            }

            // ---- deferred PV of tile j-1 ----
            if (j > 0)
                pv_mma(oacc, pp, vsb + (uint32_t)(((j - 1) % 3) << 13), rowv_b, cbv_b);

            // ---- causal mask ----
            if (n0 + 63 > mw) {
                int mA = mw + (lane >> 2), mB = mA + 8;
#pragma unroll
                for (int nt = 0; nt < 8; nt++) {
                    int n = n0 + (nt << 3) + ((lane & 3) << 1);
                    if (n     > mA) sacc[nt][0] = -1e30f;
                    if (n + 1 > mA) sacc[nt][1] = -1e30f;
                    if (n     > mB) sacc[nt][2] = -1e30f;
                    if (n + 1 > mB) sacc[nt][3] = -1e30f;
                }
            }

            // ---- max reduce (log2 units) ----
            float mx0 = -1e30f, mx1 = -1e30f;
#pragma unroll
            for (int nt = 0; nt < 8; nt++) {
                mx0 = fmaxf(mx0, fmaxf(sacc[nt][0], sacc[nt][1]));
                mx1 = fmaxf(mx1, fmaxf(sacc[nt][2], sacc[nt][3]));
            }
            mx0 = fmaxf(mx0, __shfl_xor_sync(0xffffffffu, mx0, 1));
            mx0 = fmaxf(mx0, __shfl_xor_sync(0xffffffffu, mx0, 2));
            mx1 = fmaxf(mx1, __shfl_xor_sync(0xffffffffu, mx1, 1));
            mx1 = fmaxf(mx1, __shfl_xor_sync(0xffffffffu, mx1, 2));
            float mn0 = fmaxf(mrow0, mx0), mn1 = fmaxf(mrow1, mx1);
            float a0 = exp2f(mrow0 - mn0), a1 = exp2f(mrow1 - mn1);
            mrow0 = mn0; mrow1 = mn1;

            // rescale AFTER PV_{j-1} (telescoping); lacc tracks oacc exactly
#pragma unroll
            for (int nt = 0; nt < 8; nt++) {
                oacc[nt][0] *= a0; oacc[nt][1] *= a0;
                oacc[nt][2] *= a1; oacc[nt][3] *= a1;
            }
            lacc[0] *= a0; lacc[1] *= a0;
            lacc[2] *= a1; lacc[3] *= a1;

            // ---- P = 2^(S - m) directly in fp16 (f16x2 MUFU) ----
#pragma unroll
            for (int kvs = 0; kvs < 4; kvs++) {
                pp[kvs][0] = ex2h2(pkh2(sacc[2 * kvs][0] - mn0,     sacc[2 * kvs][1] - mn0));
                pp[kvs][1] = ex2h2(pkh2(sacc[2 * kvs][2] - mn1,     sacc[2 * kvs][3] - mn1));
                pp[kvs][2] = ex2h2(pkh2(sacc[2 * kvs + 1][0] - mn0, sacc[2 * kvs + 1][1] - mn0));
                pp[kvs][3] = ex2h2(pkh2(sacc[2 * kvs + 1][2] - mn1, sacc[2 * kvs + 1][3] - mn1));
            }

            // ---- l += P @ ones (row sums on the tensor pipe, no shfl) ----
#pragma unroll
            for (int kvs = 0; kvs < 4; kvs++)
                mma_f16(lacc, pp[kvs], HONES, HONES);
        } else if (!flushed) {
            pv_mma(oacc, pp, vsb + (uint32_t)(((j - 1) % 3) << 13), rowv_b, cbv_b);
            flushed = true;
        }
    }
    if (!flushed)
        pv_mma(oacc, pp, vsb + (uint32_t)(((nkv - 1) % 3) << 13), rowv_b, cbv_b);

    float inv0 = 1.0f / lacc[0], inv1 = 1.0f / lacc[2];
    int mA = mw + (lane >> 2);
    size_t r0 = (size_t)(b * Tc + mA) * Cc + (h << 6) + ((lane & 3) << 1);
    size_t r1 = r0 + (size_t)8 * Cc;
#pragma unroll
    for (int nt = 0; nt < 8; nt++) {
        *(__half2*)&Y[r0 + (nt << 3)] = __floats2half2_rn(oacc[nt][0] * inv0, oacc[nt][1] * inv0);
        *(__half2*)&Y[r1 + (nt << 3)] = __floats2half2_rn(oacc[nt][2] * inv1, oacc[nt][3] * inv1);
    }
}

// ============================================================================
extern "C" void kernel_launch(void* const* d_in, const int* in_sizes, int n_in,
                              void* d_out, int out_size)
{
    const float* x  = (const float*)d_in[0];
    const float* Wk = (const float*)d_in[1];
    const float* bk = (const float*)d_in[2];
    const float* Wq = (const float*)d_in[3];
    const float* bq = (const float*)d_in[4];
    const float* Wv = (const float*)d_in[5];
    const float* bv = (const float*)d_in[6];
    const float* Wp = (const float*)d_in[7];
    const float* bp = (const float*)d_in[8];
    float* out = (float*)d_out;

    __half *xh, *wqh, *wkh, *wvh, *wph, *qh, *kh, *vh, *yh;
    cudaGetSymbolAddress((void**)&xh,  g_xh);
    cudaGetSymbolAddress((void**)&wqh, g_wqh);
    cudaGetSymbolAddress((void**)&wkh, g_wkh);
    cudaGetSymbolAddress((void**)&wvh, g_wvh);
    cudaGetSymbolAddress((void**)&wph, g_wph);
    cudaGetSymbolAddress((void**)&qh,  g_qh);
    cudaGetSymbolAddress((void**)&kh,  g_kh);
    cudaGetSymbolAddress((void**)&vh,  g_vh);
    cudaGetSymbolAddress((void**)&yh,  g_yh);

    cudaFuncSetAttribute(gemm_h<0>, cudaFuncAttributeMaxDynamicSharedMemorySize, GSMEM);
    cudaFuncSetAttribute(gemm_h<1>, cudaFuncAttributeMaxDynamicSharedMemorySize, GSMEM);
    cudaFuncSetAttribute(flash_attn, cudaFuncAttributeMaxDynamicSharedMemorySize, FSMEM);

    const int ntot = NX4 + 4 * NW4;
    cvt_all<<<(ntot + 255) / 256, 256>>>(x, Wq, Wk, Wv, Wp, xh, wqh, wkh, wvh, wph);

    dim3 gq((3 * Cc) / 128, Mtot / 128);   // (24, 32)
    gemm_h<0><<<gq, 256, GSMEM>>>(xh, wqh, wkh, wvh, bq, bk, bv, qh, kh, vh);

    dim3 fg(Tc / 128, Bc * Hc);            // (16, 32)
    flash_attn<<<fg, 256, FSMEM>>>(qh, kh, vh, yh);

    dim3 gp(Cc / 128, Mtot / 128);         // (8, 32)
    gemm_h<1><<<gp, 256, GSMEM>>>(yh, wph, wph, wph, bp, bp, bp, out, out, out);
}